// round 2
// baseline (speedup 1.0000x reference)
#include <cuda_runtime.h>
#include <math.h>

// ---------------- problem constants ----------------
#define B_   2
#define S_   2048
#define DIM_ 1024
#define H_   16
#define KVH_ 4
#define HD_  64
#define I_   2048
#define N_   16
#define DTR_ 64
#define K_   4
#define MTOT (B_*S_)          // 4096
#define EPSF 1.1920929e-07f

// ---------------- scratch (static device, no allocs) ----------------
__device__ float g_mp[MTOT*(size_t)(2*I_)];      // x @ W_mamba.T  (4096 x 4096)
__device__ float g_qh[MTOT*(size_t)DIM_];        // x @ W_q.T
__device__ float g_kv[MTOT*(size_t)(2*KVH_*HD_)];// x @ W_kv.T (k|v)
__device__ float g_qn[MTOT*(size_t)DIM_];        // normed+roped q
__device__ float g_kn[MTOT*(size_t)(KVH_*HD_)];  // normed+roped k
__device__ float g_attn[MTOT*(size_t)DIM_];      // attention out
__device__ float g_u[MTOT*(size_t)I_];           // conv+silu
__device__ float g_params[MTOT*(size_t)96];      // xproj out
__device__ float g_delta[MTOT*(size_t)I_];       // softplus(dt)
__device__ float g_y[MTOT*(size_t)I_];           // scan out (gated)
__device__ float g_merged[MTOT*(size_t)DIM_];    // alpha-merged
__device__ float g_rcos[S_*32];
__device__ float g_rsin[S_*32];

// ---------------- helpers ----------------
__device__ __forceinline__ float sigmoidf_(float x){ return 1.f/(1.f+expf(-x)); }
__device__ __forceinline__ float softplusf_(float x){ return fmaxf(x,0.f)+log1pf(expf(-fabsf(x))); }

// ---------------- generic SGEMM: C = A(M,K; lda) * W(N,K)^T ----------------
// epilogue: 0 = plain, 1 = softplus(acc + bias[c]), 2 = alpha*aux + (1-alpha)*acc
__global__ __launch_bounds__(256)
void sgemm128(const float* __restrict__ A, int lda,
              const float* __restrict__ W,
              float* __restrict__ C, int ldc,
              int M, int Nn, int K,
              int ep,
              const float* __restrict__ bias,
              const float* __restrict__ aux,
              const float* __restrict__ alpha_p)
{
    __shared__ float As[8][128];
    __shared__ float Ws[8][128];
    const int tid = threadIdx.x;
    const int ty = tid >> 4, tx = tid & 15;
    const int bm = blockIdx.y * 128;
    const int bn = blockIdx.x * 128;

    float acc[8][8];
    #pragma unroll
    for (int i = 0; i < 8; i++)
        #pragma unroll
        for (int j = 0; j < 8; j++) acc[i][j] = 0.f;

    const int lr = tid >> 1;            // 0..127
    const int lk = (tid & 1) << 2;      // 0 or 4
    const float* Aptr = A + (size_t)(bm + lr) * lda + lk;
    const float* Wptr = W + (size_t)(bn + lr) * K + lk;
    const bool wvalid = (bn + lr) < Nn;

    for (int k0 = 0; k0 < K; k0 += 8) {
        float4 av = *(const float4*)(Aptr + k0);
        float4 wv = wvalid ? *(const float4*)(Wptr + k0) : make_float4(0.f,0.f,0.f,0.f);
        __syncthreads();
        As[lk+0][lr]=av.x; As[lk+1][lr]=av.y; As[lk+2][lr]=av.z; As[lk+3][lr]=av.w;
        Ws[lk+0][lr]=wv.x; Ws[lk+1][lr]=wv.y; Ws[lk+2][lr]=wv.z; Ws[lk+3][lr]=wv.w;
        __syncthreads();
        #pragma unroll
        for (int k = 0; k < 8; k++) {
            float ra[8], rw[8];
            *(float4*)(ra)   = *(const float4*)&As[k][ty*4];
            *(float4*)(ra+4) = *(const float4*)&As[k][64+ty*4];
            *(float4*)(rw)   = *(const float4*)&Ws[k][tx*4];
            *(float4*)(rw+4) = *(const float4*)&Ws[k][64+tx*4];
            #pragma unroll
            for (int i = 0; i < 8; i++)
                #pragma unroll
                for (int j = 0; j < 8; j++)
                    acc[i][j] += ra[i]*rw[j];
        }
    }

    float alpha = 0.f;
    if (ep == 2) alpha = sigmoidf_(alpha_p[0]);

    #pragma unroll
    for (int i = 0; i < 8; i++) {
        int r = bm + ((i < 4) ? (ty*4 + i) : (64 + ty*4 + i - 4));
        #pragma unroll
        for (int j = 0; j < 8; j++) {
            int c = bn + ((j < 4) ? (tx*4 + j) : (64 + tx*4 + j - 4));
            if (c < Nn) {
                float v = acc[i][j];
                if (ep == 1) { v += bias[c]; v = softplusf_(v); }
                else if (ep == 2) { v = alpha*aux[(size_t)r*ldc + c] + (1.f-alpha)*v; }
                C[(size_t)r*ldc + c] = v;
            }
        }
    }
}

// ---------------- RoPE tables (fp64 for accuracy) ----------------
__global__ void rope_init_k()
{
    int idx = blockIdx.x*256 + threadIdx.x;
    if (idx >= S_*32) return;
    int s = idx >> 5, d = idx & 31;
    double inv = exp(-((double)(2*d)/64.0) * log(10000.0));
    double a = (double)s * inv;
    g_rcos[idx] = (float)cos(a);
    g_rsin[idx] = (float)sin(a);
}

// ---------------- RMSNorm + RoPE (+q_gain) for q and k ----------------
// one warp per (token, head); heads 0..15 = q, 16..19 = k
__global__ __launch_bounds__(256)
void qk_norm_rope_k(const float* __restrict__ q_gain)
{
    int task = blockIdx.x*8 + (threadIdx.x >> 5);
    int lane = threadIdx.x & 31;
    int m = task / 20, hh = task % 20;
    int s = m & (S_-1);

    const float* src; float* dst;
    if (hh < 16) { src = g_qh + (size_t)m*DIM_ + hh*64; dst = g_qn + (size_t)m*DIM_ + hh*64; }
    else         { src = g_kv + (size_t)m*512 + (hh-16)*64; dst = g_kn + (size_t)m*256 + (hh-16)*64; }

    float v0 = src[lane], v1 = src[lane+32];
    float ss = v0*v0 + v1*v1;
    #pragma unroll
    for (int off = 16; off >= 1; off >>= 1) ss += __shfl_xor_sync(0xffffffffu, ss, off);
    float r = rsqrtf(ss/64.f + EPSF);
    v0 *= r; v1 *= r;
    float c  = g_rcos[s*32 + lane];
    float sn = g_rsin[s*32 + lane];
    float o0 =  v0*c + v1*sn;
    float o1 = -v0*sn + v1*c;
    if (hh < 16) { float g = q_gain[hh]; o0 *= g; o1 *= g; }
    dst[lane] = o0; dst[lane+32] = o1;
}

// ---------------- causal GQA flash attention, fp32, 64x64 tiles ----------------
__global__ __launch_bounds__(256)
void flash_attn_k()
{
    __shared__ float Qs[64][64];   // [d][r]
    __shared__ float KPs[64][64];  // K: [d][c], then reused as P^T: [c][r]
    __shared__ float Vs[64][64];   // [c][dv]

    const int tid = threadIdx.x, ty = tid >> 4, tx = tid & 15;
    const int qt = blockIdx.x, h = blockIdx.y, b = blockIdx.z;
    const int kh = h >> 2;
    const int q0 = qt << 6;

    #pragma unroll
    for (int l = 0; l < 4; l++) {
        int fid = tid + l*256;
        int r = fid >> 4, dq = (fid & 15) << 2;
        float4 v = *(const float4*)(g_qn + ((size_t)(b*S_ + q0 + r))*DIM_ + h*64 + dq);
        Qs[dq][r]=v.x; Qs[dq+1][r]=v.y; Qs[dq+2][r]=v.z; Qs[dq+3][r]=v.w;
    }

    float m_i[4], l_i[4], acc[4][4];
    #pragma unroll
    for (int i = 0; i < 4; i++) { m_i[i] = -1e30f; l_i[i] = 0.f;
        #pragma unroll
        for (int j = 0; j < 4; j++) acc[i][j] = 0.f; }

    for (int kt = 0; kt <= qt; kt++) {
        __syncthreads();
        #pragma unroll
        for (int l = 0; l < 4; l++) {
            int fid = tid + l*256;
            int c = fid >> 4, dq = (fid & 15) << 2;
            size_t krow = (size_t)(b*S_ + (kt<<6) + c);
            float4 kvv = *(const float4*)(g_kn + krow*256 + kh*64 + dq);
            KPs[dq][c]=kvv.x; KPs[dq+1][c]=kvv.y; KPs[dq+2][c]=kvv.z; KPs[dq+3][c]=kvv.w;
            *(float4*)&Vs[c][dq] = *(const float4*)(g_kv + krow*512 + 256 + kh*64 + dq);
        }
        __syncthreads();

        float sc[4][4];
        #pragma unroll
        for (int i = 0; i < 4; i++)
            #pragma unroll
            for (int j = 0; j < 4; j++) sc[i][j] = 0.f;
        #pragma unroll
        for (int d = 0; d < 64; d++) {
            float ra[4], rb[4];
            *(float4*)ra = *(const float4*)&Qs[d][ty<<2];
            *(float4*)rb = *(const float4*)&KPs[d][tx<<2];
            #pragma unroll
            for (int i = 0; i < 4; i++)
                #pragma unroll
                for (int j = 0; j < 4; j++) sc[i][j] += ra[i]*rb[j];
        }
        #pragma unroll
        for (int i = 0; i < 4; i++)
            #pragma unroll
            for (int j = 0; j < 4; j++) sc[i][j] *= 0.125f;
        if (kt == qt) {
            #pragma unroll
            for (int i = 0; i < 4; i++)
                #pragma unroll
                for (int j = 0; j < 4; j++)
                    if ((kt*64 + tx*4 + j) > (q0 + ty*4 + i)) sc[i][j] = -1e30f;
        }

        #pragma unroll
        for (int i = 0; i < 4; i++) {
            float rm = fmaxf(fmaxf(sc[i][0], sc[i][1]), fmaxf(sc[i][2], sc[i][3]));
            #pragma unroll
            for (int off = 8; off >= 1; off >>= 1) rm = fmaxf(rm, __shfl_xor_sync(0xffffffffu, rm, off));
            float nm = fmaxf(m_i[i], rm);
            float corr = expf(m_i[i] - nm);
            float rs = 0.f;
            #pragma unroll
            for (int j = 0; j < 4; j++) { sc[i][j] = expf(sc[i][j] - nm); rs += sc[i][j]; }
            #pragma unroll
            for (int off = 8; off >= 1; off >>= 1) rs += __shfl_xor_sync(0xffffffffu, rs, off);
            l_i[i] = l_i[i]*corr + rs;
            m_i[i] = nm;
            #pragma unroll
            for (int j = 0; j < 4; j++) acc[i][j] *= corr;
        }

        __syncthreads();
        #pragma unroll
        for (int i = 0; i < 4; i++)
            #pragma unroll
            for (int j = 0; j < 4; j++) KPs[tx*4+j][ty*4+i] = sc[i][j];
        __syncthreads();

        #pragma unroll
        for (int c = 0; c < 64; c++) {
            float ra[4], rv[4];
            *(float4*)ra = *(const float4*)&KPs[c][ty<<2];
            *(float4*)rv = *(const float4*)&Vs[c][tx<<2];
            #pragma unroll
            for (int i = 0; i < 4; i++)
                #pragma unroll
                for (int j = 0; j < 4; j++) acc[i][j] += ra[i]*rv[j];
        }
    }

    #pragma unroll
    for (int i = 0; i < 4; i++) {
        float inv = 1.f / l_i[i];
        #pragma unroll
        for (int j = 0; j < 4; j++)
            g_attn[((size_t)(b*S_ + q0 + ty*4 + i))*DIM_ + h*64 + tx*4 + j] = acc[i][j]*inv;
    }
}

// ---------------- depthwise causal conv (K=4) + SiLU ----------------
__global__ __launch_bounds__(256)
void conv_silu_k(const float* __restrict__ conv_w, const float* __restrict__ conv_b)
{
    int idx = blockIdx.x*256 + threadIdx.x;      // m*I + i
    int m = idx >> 11, i = idx & (I_-1);
    int b = m >> 11, s = m & (S_-1);
    float acc = conv_b[i];
    #pragma unroll
    for (int k = 0; k < K_; k++) {
        int sp = s - 3 + k;
        if (sp >= 0) acc += g_mp[((size_t)(b*S_ + sp))*(2*I_) + i] * conv_w[i*K_ + k];
    }
    g_u[idx] = acc * sigmoidf_(acc);
}

// ---------------- SSM sequential scan, fused D/gate epilogue ----------------
// lane group of 16 per (b,i): lane n holds state_n
__global__ __launch_bounds__(256)
void ssm_scan_k(const float* __restrict__ A_log, const float* __restrict__ Dvec)
{
    int gtid = blockIdx.x*256 + threadIdx.x;
    int grp = gtid >> 4, n = gtid & 15;
    int b = grp >> 11, i = grp & (I_-1);

    float A  = -expf(A_log[i*N_ + n]);
    float Dv = Dvec[i];
    float state = 0.f;
    size_t base = (size_t)b * S_;

    for (int t = 0; t < S_; t++) {
        size_t m = base + t;
        float d  = g_delta[m*I_ + i];
        float uu = g_u[m*I_ + i];
        float Bv = g_params[m*96 + 64 + n];
        float Cv = g_params[m*96 + 80 + n];
        state = state*expf(d*A) + d*Bv*uu;
        float yv = state*Cv;
        #pragma unroll
        for (int off = 8; off >= 1; off >>= 1) yv += __shfl_xor_sync(0xffffffffu, yv, off);
        if (n == 0) {
            float g = g_mp[m*(2*I_) + I_ + i];
            g_y[m*I_ + i] = (yv + uu*Dv) * g * sigmoidf_(g);
        }
    }
}

// ---------------- launcher ----------------
extern "C" void kernel_launch(void* const* d_in, const int* in_sizes, int n_in,
                              void* d_out, int out_size)
{
    const float* x        = (const float*)d_in[0];
    const float* W_mamba  = (const float*)d_in[1];
    const float* W_q      = (const float*)d_in[2];
    const float* W_kv     = (const float*)d_in[3];
    const float* q_gain   = (const float*)d_in[4];
    const float* conv_w   = (const float*)d_in[5];
    const float* conv_b   = (const float*)d_in[6];
    const float* W_xproj  = (const float*)d_in[7];
    const float* W_dt     = (const float*)d_in[8];
    const float* b_dt     = (const float*)d_in[9];
    const float* A_log    = (const float*)d_in[10];
    const float* Dvec     = (const float*)d_in[11];
    const float* W_mout   = (const float*)d_in[12];
    const float* W_proj   = (const float*)d_in[13];
    const float* m_alpha  = (const float*)d_in[14];
    float* out = (float*)d_out;

    float *p_mp, *p_qh, *p_kv, *p_attn, *p_u, *p_params, *p_delta, *p_y, *p_merged;
    cudaGetSymbolAddress((void**)&p_mp, g_mp);
    cudaGetSymbolAddress((void**)&p_qh, g_qh);
    cudaGetSymbolAddress((void**)&p_kv, g_kv);
    cudaGetSymbolAddress((void**)&p_attn, g_attn);
    cudaGetSymbolAddress((void**)&p_u, g_u);
    cudaGetSymbolAddress((void**)&p_params, g_params);
    cudaGetSymbolAddress((void**)&p_delta, g_delta);
    cudaGetSymbolAddress((void**)&p_y, g_y);
    cudaGetSymbolAddress((void**)&p_merged, g_merged);

    // 0. rope tables
    rope_init_k<<<(S_*32 + 255)/256, 256>>>();

    // 1. mp = x @ W_mamba.T  (4096 x 4096 x 1024)
    sgemm128<<<dim3(32,32), 256>>>(x, DIM_, W_mamba, p_mp, 2*I_, MTOT, 2*I_, DIM_, 0, nullptr, nullptr, nullptr);
    // 2. q = x @ W_q.T
    sgemm128<<<dim3(8,32), 256>>>(x, DIM_, W_q, p_qh, DIM_, MTOT, DIM_, DIM_, 0, nullptr, nullptr, nullptr);
    // 3. kv = x @ W_kv.T
    sgemm128<<<dim3(4,32), 256>>>(x, DIM_, W_kv, p_kv, 512, MTOT, 512, DIM_, 0, nullptr, nullptr, nullptr);

    // 4. rmsnorm + rope
    qk_norm_rope_k<<<(MTOT*20)/8, 256>>>(q_gain);

    // 5. causal GQA attention
    flash_attn_k<<<dim3(S_/64, H_, B_), 256>>>();

    // 6. conv + silu
    conv_silu_k<<<(MTOT*I_)/256, 256>>>(conv_w, conv_b);

    // 7. params = u @ W_xproj.T  (4096 x 96 x 2048)
    sgemm128<<<dim3(1,32), 256>>>(p_u, I_, W_xproj, p_params, 96, MTOT, 96, I_, 0, nullptr, nullptr, nullptr);

    // 8. delta = softplus(dt_low @ W_dt.T + b_dt)  (4096 x 2048 x 64)
    sgemm128<<<dim3(16,32), 256>>>(p_params, 96, W_dt, p_delta, I_, MTOT, I_, DTR_, 1, b_dt, nullptr, nullptr);

    // 9. scan (+ D skip + gate)
    ssm_scan_k<<<(MTOT*I_*N_ / I_ / N_) * (I_*N_) / (256*256) == 0 ? 256 : (B_*I_*N_)/256, 256>>>(A_log, Dvec);

    // 10. merged = alpha*attn + (1-alpha) * (y @ W_mamba_out.T)
    sgemm128<<<dim3(8,32), 256>>>(p_y, I_, W_mout, p_merged, DIM_, MTOT, DIM_, I_, 2, nullptr, p_attn, m_alpha);

    // 11. out = merged @ W_proj.T
    sgemm128<<<dim3(8,32), 256>>>(p_merged, DIM_, W_proj, out, DIM_, MTOT, DIM_, DIM_, 0, nullptr, nullptr, nullptr);
}

// round 3
// speedup vs baseline: 1.3029x; 1.3029x over previous
#include <cuda_runtime.h>
#include <math.h>
#include <stdint.h>

// ---------------- problem constants ----------------
#define B_   2
#define S_   2048
#define DIM_ 1024
#define H_   16
#define KVH_ 4
#define HD_  64
#define I_   2048
#define N_   16
#define DTR_ 64
#define K_   4
#define MTOT (B_*S_)          // 4096
#define EPSF 1.1920929e-07f
#define LDS_ 136              // smem row stride (floats): 128 + 8 pad -> conflict-free frags

// ---------------- scratch (static device, no allocs) ----------------
__device__ float g_mp[MTOT*(size_t)(2*I_)];      // x @ W_mamba.T  (4096 x 4096)
__device__ float g_qh[MTOT*(size_t)DIM_];        // x @ W_q.T
__device__ float g_kv[MTOT*(size_t)(2*KVH_*HD_)];// x @ W_kv.T (k|v)
__device__ float g_qn[MTOT*(size_t)DIM_];        // normed+roped q
__device__ float g_kn[MTOT*(size_t)(KVH_*HD_)];  // normed+roped k
__device__ float g_attn[MTOT*(size_t)DIM_];      // attention out
__device__ float g_u[MTOT*(size_t)I_];           // conv+silu
__device__ float g_params[MTOT*(size_t)96];      // xproj out
__device__ float g_delta[MTOT*(size_t)I_];       // softplus(dt)
__device__ float g_y[MTOT*(size_t)I_];           // scan out (gated)
__device__ float g_merged[MTOT*(size_t)DIM_];    // alpha-merged
__device__ float g_rcos[S_*32];
__device__ float g_rsin[S_*32];

// ---------------- helpers ----------------
__device__ __forceinline__ float sigmoidf_(float x){ return 1.f/(1.f+expf(-x)); }
__device__ __forceinline__ float softplusf_(float x){ return fmaxf(x,0.f)+log1pf(expf(-fabsf(x))); }
__device__ __forceinline__ float tf32r_(float x){
    uint32_t u; asm("cvt.rna.tf32.f32 %0, %1;" : "=r"(u) : "f"(x));
    return __uint_as_float(u);
}
__device__ __forceinline__ void mma_tf32_(float4& d,
    uint32_t a0, uint32_t a1, uint32_t a2, uint32_t a3,
    uint32_t b0, uint32_t b1)
{
    asm volatile("mma.sync.aligned.m16n8k8.row.col.f32.tf32.tf32.f32 "
        "{%0,%1,%2,%3}, {%4,%5,%6,%7}, {%8,%9}, {%0,%1,%2,%3};\n"
        : "+f"(d.x), "+f"(d.y), "+f"(d.z), "+f"(d.w)
        : "r"(a0), "r"(a1), "r"(a2), "r"(a3), "r"(b0), "r"(b1));
}

// ---------------- TF32 tensor-core GEMM: C = A(M,K; lda) * W(N,K)^T ----------------
// Block tile 128x128, K-tile 32, 8 warps (2m x 4n), warp tile 64x32.
// epilogue: 0 = plain, 1 = softplus(acc + bias[c]), 2 = alpha*aux + (1-alpha)*acc
__global__ __launch_bounds__(256)
void tgemm(const float* __restrict__ A, int lda,
           const float* __restrict__ W,
           float* __restrict__ C, int ldc,
           int M, int Nn, int K, int ep,
           const float* __restrict__ bias,
           const float* __restrict__ aux,
           const float* __restrict__ alpha_p)
{
    __shared__ float As[32*LDS_];   // [k][m]
    __shared__ float Ws[32*LDS_];   // [k][n]

    const int tid = threadIdx.x;
    const int bm = blockIdx.y * 128;
    const int bn = blockIdx.x * 128;
    const int warp = tid >> 5, lane = tid & 31;
    const int g = lane >> 2, tig = lane & 3;
    const int wm = (warp >> 2) * 64;   // 0 / 64
    const int wn = (warp & 3) * 32;    // 0..96

    // staging assignment: each thread owns (row lr, k-segment lk..lk+15)
    const int lr = tid >> 1;           // 0..127
    const int lk = (tid & 1) * 16;     // 0 / 16
    const float* Ap = A + (size_t)(bm + lr) * lda + lk;
    const float* Wp = W + (size_t)(bn + lr) * K + lk;
    const bool wvalid = (bn + lr) < Nn;

    float4 acc[4][4];
    #pragma unroll
    for (int i = 0; i < 4; i++)
        #pragma unroll
        for (int j = 0; j < 4; j++) acc[i][j] = make_float4(0.f,0.f,0.f,0.f);

    float4 ra[4], rw[4];
    #pragma unroll
    for (int q = 0; q < 4; q++) {
        ra[q] = *(const float4*)(Ap + q*4);
        rw[q] = wvalid ? *(const float4*)(Wp + q*4) : make_float4(0.f,0.f,0.f,0.f);
    }

    for (int kt = 0; kt < K; kt += 32) {
        __syncthreads();
        #pragma unroll
        for (int q = 0; q < 4; q++) {
            int kk = lk + q*4;
            As[(kk+0)*LDS_ + lr] = tf32r_(ra[q].x);
            As[(kk+1)*LDS_ + lr] = tf32r_(ra[q].y);
            As[(kk+2)*LDS_ + lr] = tf32r_(ra[q].z);
            As[(kk+3)*LDS_ + lr] = tf32r_(ra[q].w);
            Ws[(kk+0)*LDS_ + lr] = tf32r_(rw[q].x);
            Ws[(kk+1)*LDS_ + lr] = tf32r_(rw[q].y);
            Ws[(kk+2)*LDS_ + lr] = tf32r_(rw[q].z);
            Ws[(kk+3)*LDS_ + lr] = tf32r_(rw[q].w);
        }
        __syncthreads();

        if (kt + 32 < K) {
            const float* Ap2 = Ap + kt + 32;
            const float* Wp2 = Wp + kt + 32;
            #pragma unroll
            for (int q = 0; q < 4; q++) {
                ra[q] = *(const float4*)(Ap2 + q*4);
                rw[q] = wvalid ? *(const float4*)(Wp2 + q*4) : make_float4(0.f,0.f,0.f,0.f);
            }
        }

        #pragma unroll
        for (int k0 = 0; k0 < 32; k0 += 8) {
            uint32_t af[4][4], bf[4][2];
            const float* a_r0 = &As[(k0+tig  )*LDS_ + wm + g];
            const float* a_r1 = &As[(k0+tig+4)*LDS_ + wm + g];
            #pragma unroll
            for (int mt = 0; mt < 4; mt++) {
                af[mt][0] = __float_as_uint(a_r0[mt*16    ]);
                af[mt][1] = __float_as_uint(a_r0[mt*16 + 8]);
                af[mt][2] = __float_as_uint(a_r1[mt*16    ]);
                af[mt][3] = __float_as_uint(a_r1[mt*16 + 8]);
            }
            const float* b_r0 = &Ws[(k0+tig  )*LDS_ + wn + g];
            const float* b_r1 = &Ws[(k0+tig+4)*LDS_ + wn + g];
            #pragma unroll
            for (int nt = 0; nt < 4; nt++) {
                bf[nt][0] = __float_as_uint(b_r0[nt*8]);
                bf[nt][1] = __float_as_uint(b_r1[nt*8]);
            }
            #pragma unroll
            for (int mt = 0; mt < 4; mt++)
                #pragma unroll
                for (int nt = 0; nt < 4; nt++)
                    mma_tf32_(acc[mt][nt], af[mt][0], af[mt][1], af[mt][2], af[mt][3],
                              bf[nt][0], bf[nt][1]);
        }
    }

    float alpha = 0.f;
    if (ep == 2) alpha = sigmoidf_(alpha_p[0]);

    #pragma unroll
    for (int mt = 0; mt < 4; mt++) {
        int r0 = bm + wm + mt*16 + g;
        #pragma unroll
        for (int nt = 0; nt < 4; nt++) {
            int c0 = bn + wn + nt*8 + 2*tig;
            if (c0 < Nn) {
                float v0 = acc[mt][nt].x, v1 = acc[mt][nt].y;
                float v2 = acc[mt][nt].z, v3 = acc[mt][nt].w;
                if (ep == 1) {
                    float b0v = bias[c0], b1v = bias[c0+1];
                    v0 = softplusf_(v0 + b0v); v1 = softplusf_(v1 + b1v);
                    v2 = softplusf_(v2 + b0v); v3 = softplusf_(v3 + b1v);
                } else if (ep == 2) {
                    size_t o0 = (size_t)r0*ldc + c0, o1 = (size_t)(r0+8)*ldc + c0;
                    v0 = alpha*aux[o0]   + (1.f-alpha)*v0;
                    v1 = alpha*aux[o0+1] + (1.f-alpha)*v1;
                    v2 = alpha*aux[o1]   + (1.f-alpha)*v2;
                    v3 = alpha*aux[o1+1] + (1.f-alpha)*v3;
                }
                *(float2*)(C + (size_t)r0*ldc + c0)     = make_float2(v0, v1);
                *(float2*)(C + (size_t)(r0+8)*ldc + c0) = make_float2(v2, v3);
            }
        }
    }
}

// ---------------- RoPE tables (fp64 for accuracy) ----------------
__global__ void rope_init_k()
{
    int idx = blockIdx.x*256 + threadIdx.x;
    if (idx >= S_*32) return;
    int s = idx >> 5, d = idx & 31;
    double inv = exp(-((double)(2*d)/64.0) * log(10000.0));
    double a = (double)s * inv;
    g_rcos[idx] = (float)cos(a);
    g_rsin[idx] = (float)sin(a);
}

// ---------------- RMSNorm + RoPE (+q_gain) for q and k ----------------
__global__ __launch_bounds__(256)
void qk_norm_rope_k(const float* __restrict__ q_gain)
{
    int task = blockIdx.x*8 + (threadIdx.x >> 5);
    int lane = threadIdx.x & 31;
    int m = task / 20, hh = task % 20;
    int s = m & (S_-1);

    const float* src; float* dst;
    if (hh < 16) { src = g_qh + (size_t)m*DIM_ + hh*64; dst = g_qn + (size_t)m*DIM_ + hh*64; }
    else         { src = g_kv + (size_t)m*512 + (hh-16)*64; dst = g_kn + (size_t)m*256 + (hh-16)*64; }

    float v0 = src[lane], v1 = src[lane+32];
    float ss = v0*v0 + v1*v1;
    #pragma unroll
    for (int off = 16; off >= 1; off >>= 1) ss += __shfl_xor_sync(0xffffffffu, ss, off);
    float r = rsqrtf(ss/64.f + EPSF);
    v0 *= r; v1 *= r;
    float c  = g_rcos[s*32 + lane];
    float sn = g_rsin[s*32 + lane];
    float o0 =  v0*c + v1*sn;
    float o1 = -v0*sn + v1*c;
    if (hh < 16) { float g = q_gain[hh]; o0 *= g; o1 *= g; }
    dst[lane] = o0; dst[lane+32] = o1;
}

// ---------------- causal GQA flash attention, fp32, 64x64 tiles ----------------
__global__ __launch_bounds__(256)
void flash_attn_k()
{
    __shared__ float Qs[64][64];
    __shared__ float KPs[64][64];
    __shared__ float Vs[64][64];

    const int tid = threadIdx.x, ty = tid >> 4, tx = tid & 15;
    const int qt = blockIdx.x, h = blockIdx.y, b = blockIdx.z;
    const int kh = h >> 2;
    const int q0 = qt << 6;

    #pragma unroll
    for (int l = 0; l < 4; l++) {
        int fid = tid + l*256;
        int r = fid >> 4, dq = (fid & 15) << 2;
        float4 v = *(const float4*)(g_qn + ((size_t)(b*S_ + q0 + r))*DIM_ + h*64 + dq);
        Qs[dq][r]=v.x; Qs[dq+1][r]=v.y; Qs[dq+2][r]=v.z; Qs[dq+3][r]=v.w;
    }

    float m_i[4], l_i[4], acc[4][4];
    #pragma unroll
    for (int i = 0; i < 4; i++) { m_i[i] = -1e30f; l_i[i] = 0.f;
        #pragma unroll
        for (int j = 0; j < 4; j++) acc[i][j] = 0.f; }

    for (int kt = 0; kt <= qt; kt++) {
        __syncthreads();
        #pragma unroll
        for (int l = 0; l < 4; l++) {
            int fid = tid + l*256;
            int c = fid >> 4, dq = (fid & 15) << 2;
            size_t krow = (size_t)(b*S_ + (kt<<6) + c);
            float4 kvv = *(const float4*)(g_kn + krow*256 + kh*64 + dq);
            KPs[dq][c]=kvv.x; KPs[dq+1][c]=kvv.y; KPs[dq+2][c]=kvv.z; KPs[dq+3][c]=kvv.w;
            *(float4*)&Vs[c][dq] = *(const float4*)(g_kv + krow*512 + 256 + kh*64 + dq);
        }
        __syncthreads();

        float sc[4][4];
        #pragma unroll
        for (int i = 0; i < 4; i++)
            #pragma unroll
            for (int j = 0; j < 4; j++) sc[i][j] = 0.f;
        #pragma unroll
        for (int d = 0; d < 64; d++) {
            float ra[4], rb[4];
            *(float4*)ra = *(const float4*)&Qs[d][ty<<2];
            *(float4*)rb = *(const float4*)&KPs[d][tx<<2];
            #pragma unroll
            for (int i = 0; i < 4; i++)
                #pragma unroll
                for (int j = 0; j < 4; j++) sc[i][j] += ra[i]*rb[j];
        }
        #pragma unroll
        for (int i = 0; i < 4; i++)
            #pragma unroll
            for (int j = 0; j < 4; j++) sc[i][j] *= 0.125f;
        if (kt == qt) {
            #pragma unroll
            for (int i = 0; i < 4; i++)
                #pragma unroll
                for (int j = 0; j < 4; j++)
                    if ((kt*64 + tx*4 + j) > (q0 + ty*4 + i)) sc[i][j] = -1e30f;
        }

        #pragma unroll
        for (int i = 0; i < 4; i++) {
            float rm = fmaxf(fmaxf(sc[i][0], sc[i][1]), fmaxf(sc[i][2], sc[i][3]));
            #pragma unroll
            for (int off = 8; off >= 1; off >>= 1) rm = fmaxf(rm, __shfl_xor_sync(0xffffffffu, rm, off));
            float nm = fmaxf(m_i[i], rm);
            float corr = expf(m_i[i] - nm);
            float rs = 0.f;
            #pragma unroll
            for (int j = 0; j < 4; j++) { sc[i][j] = expf(sc[i][j] - nm); rs += sc[i][j]; }
            #pragma unroll
            for (int off = 8; off >= 1; off >>= 1) rs += __shfl_xor_sync(0xffffffffu, rs, off);
            l_i[i] = l_i[i]*corr + rs;
            m_i[i] = nm;
            #pragma unroll
            for (int j = 0; j < 4; j++) acc[i][j] *= corr;
        }

        __syncthreads();
        #pragma unroll
        for (int i = 0; i < 4; i++)
            #pragma unroll
            for (int j = 0; j < 4; j++) KPs[tx*4+j][ty*4+i] = sc[i][j];
        __syncthreads();

        #pragma unroll
        for (int c = 0; c < 64; c++) {
            float ra[4], rv[4];
            *(float4*)ra = *(const float4*)&KPs[c][ty<<2];
            *(float4*)rv = *(const float4*)&Vs[c][tx<<2];
            #pragma unroll
            for (int i = 0; i < 4; i++)
                #pragma unroll
                for (int j = 0; j < 4; j++) acc[i][j] += ra[i]*rv[j];
        }
    }

    #pragma unroll
    for (int i = 0; i < 4; i++) {
        float inv = 1.f / l_i[i];
        #pragma unroll
        for (int j = 0; j < 4; j++)
            g_attn[((size_t)(b*S_ + q0 + ty*4 + i))*DIM_ + h*64 + tx*4 + j] = acc[i][j]*inv;
    }
}

// ---------------- depthwise causal conv (K=4) + SiLU ----------------
__global__ __launch_bounds__(256)
void conv_silu_k(const float* __restrict__ conv_w, const float* __restrict__ conv_b)
{
    int idx = blockIdx.x*256 + threadIdx.x;      // m*I + i
    int m = idx >> 11, i = idx & (I_-1);
    int b = m >> 11, s = m & (S_-1);
    float acc = conv_b[i];
    #pragma unroll
    for (int k = 0; k < K_; k++) {
        int sp = s - 3 + k;
        if (sp >= 0) acc += g_mp[((size_t)(b*S_ + sp))*(2*I_) + i] * conv_w[i*K_ + k];
    }
    g_u[idx] = acc * sigmoidf_(acc);
}

// ---------------- SSM sequential scan, fused D/gate epilogue ----------------
__global__ __launch_bounds__(256)
void ssm_scan_k(const float* __restrict__ A_log, const float* __restrict__ Dvec)
{
    int gtid = blockIdx.x*256 + threadIdx.x;
    int grp = gtid >> 4, n = gtid & 15;
    int b = grp >> 11, i = grp & (I_-1);

    float A  = -expf(A_log[i*N_ + n]);
    float Dv = Dvec[i];
    float state = 0.f;
    size_t base = (size_t)b * S_;

    for (int t = 0; t < S_; t++) {
        size_t m = base + t;
        float d  = g_delta[m*I_ + i];
        float uu = g_u[m*I_ + i];
        float Bv = g_params[m*96 + 64 + n];
        float Cv = g_params[m*96 + 80 + n];
        state = state*expf(d*A) + d*Bv*uu;
        float yv = state*Cv;
        #pragma unroll
        for (int off = 8; off >= 1; off >>= 1) yv += __shfl_xor_sync(0xffffffffu, yv, off);
        if (n == 0) {
            float g = g_mp[m*(2*I_) + I_ + i];
            g_y[m*I_ + i] = (yv + uu*Dv) * g * sigmoidf_(g);
        }
    }
}

// ---------------- launcher ----------------
extern "C" void kernel_launch(void* const* d_in, const int* in_sizes, int n_in,
                              void* d_out, int out_size)
{
    const float* x        = (const float*)d_in[0];
    const float* W_mamba  = (const float*)d_in[1];
    const float* W_q      = (const float*)d_in[2];
    const float* W_kv     = (const float*)d_in[3];
    const float* q_gain   = (const float*)d_in[4];
    const float* conv_w   = (const float*)d_in[5];
    const float* conv_b   = (const float*)d_in[6];
    const float* W_xproj  = (const float*)d_in[7];
    const float* W_dt     = (const float*)d_in[8];
    const float* b_dt     = (const float*)d_in[9];
    const float* A_log    = (const float*)d_in[10];
    const float* Dvec     = (const float*)d_in[11];
    const float* W_mout   = (const float*)d_in[12];
    const float* W_proj   = (const float*)d_in[13];
    const float* m_alpha  = (const float*)d_in[14];
    float* out = (float*)d_out;

    float *p_mp, *p_qh, *p_kv, *p_attn, *p_u, *p_params, *p_delta, *p_y, *p_merged;
    cudaGetSymbolAddress((void**)&p_mp, g_mp);
    cudaGetSymbolAddress((void**)&p_qh, g_qh);
    cudaGetSymbolAddress((void**)&p_kv, g_kv);
    cudaGetSymbolAddress((void**)&p_attn, g_attn);
    cudaGetSymbolAddress((void**)&p_u, g_u);
    cudaGetSymbolAddress((void**)&p_params, g_params);
    cudaGetSymbolAddress((void**)&p_delta, g_delta);
    cudaGetSymbolAddress((void**)&p_y, g_y);
    cudaGetSymbolAddress((void**)&p_merged, g_merged);

    // 0. rope tables
    rope_init_k<<<(S_*32 + 255)/256, 256>>>();

    // 1. mp = x @ W_mamba.T  (4096 x 4096 x 1024)
    tgemm<<<dim3(32,32), 256>>>(x, DIM_, W_mamba, p_mp, 2*I_, MTOT, 2*I_, DIM_, 0, nullptr, nullptr, nullptr);
    // 2. q = x @ W_q.T
    tgemm<<<dim3(8,32), 256>>>(x, DIM_, W_q, p_qh, DIM_, MTOT, DIM_, DIM_, 0, nullptr, nullptr, nullptr);
    // 3. kv = x @ W_kv.T
    tgemm<<<dim3(4,32), 256>>>(x, DIM_, W_kv, p_kv, 512, MTOT, 512, DIM_, 0, nullptr, nullptr, nullptr);

    // 4. rmsnorm + rope
    qk_norm_rope_k<<<(MTOT*20)/8, 256>>>(q_gain);

    // 5. causal GQA attention
    flash_attn_k<<<dim3(S_/64, H_, B_), 256>>>();

    // 6. conv + silu
    conv_silu_k<<<(MTOT*I_)/256, 256>>>(conv_w, conv_b);

    // 7. params = u @ W_xproj.T  (4096 x 96 x 2048)
    tgemm<<<dim3(1,32), 256>>>(p_u, I_, W_xproj, p_params, 96, MTOT, 96, I_, 0, nullptr, nullptr, nullptr);

    // 8. delta = softplus(dt_low @ W_dt.T + b_dt)  (4096 x 2048 x 64)
    tgemm<<<dim3(16,32), 256>>>(p_params, 96, W_dt, p_delta, I_, MTOT, I_, DTR_, 1, b_dt, nullptr, nullptr);

    // 9. scan (+ D skip + gate)
    ssm_scan_k<<<(B_*I_*N_)/256, 256>>>(A_log, Dvec);

    // 10. merged = alpha*attn + (1-alpha) * (y @ W_mamba_out.T)
    tgemm<<<dim3(8,32), 256>>>(p_y, I_, W_mout, p_merged, DIM_, MTOT, DIM_, I_, 2, nullptr, p_attn, m_alpha);

    // 11. out = merged @ W_proj.T
    tgemm<<<dim3(8,32), 256>>>(p_merged, DIM_, W_proj, out, DIM_, MTOT, DIM_, DIM_, 0, nullptr, nullptr, nullptr);
}

// round 4
// speedup vs baseline: 1.5205x; 1.1671x over previous
#include <cuda_runtime.h>
#include <math.h>
#include <stdint.h>

// ---------------- problem constants ----------------
#define B_   2
#define S_   2048
#define DIM_ 1024
#define H_   16
#define KVH_ 4
#define HD_  64
#define I_   2048
#define N_   16
#define DTR_ 64
#define K_   4
#define MTOT (B_*S_)          // 4096
#define EPSF 1.1920929e-07f
#define LDS_ 136              // gemm smem row stride

// ---------------- scratch (static device, no allocs) ----------------
__device__ float g_mp[MTOT*(size_t)(2*I_)];      // x @ W_mamba.T  (4096 x 4096)
__device__ float g_qh[MTOT*(size_t)DIM_];        // x @ W_q.T
__device__ float g_kv[MTOT*(size_t)(2*KVH_*HD_)];// x @ W_kv.T (k|v)
__device__ float g_qn[MTOT*(size_t)DIM_];        // normed+roped q
__device__ float g_kn[MTOT*(size_t)(KVH_*HD_)];  // normed+roped k
__device__ float g_attn[MTOT*(size_t)DIM_];      // attention out
__device__ float g_u[MTOT*(size_t)I_];           // conv+silu
__device__ float g_params[MTOT*(size_t)96];      // xproj out
__device__ float g_delta[MTOT*(size_t)I_];       // softplus(dt)
__device__ float g_y[MTOT*(size_t)I_];           // scan out (gated)
__device__ float g_merged[MTOT*(size_t)DIM_];    // alpha-merged
__device__ float g_rcos[S_*32];
__device__ float g_rsin[S_*32];

// ---------------- helpers ----------------
__device__ __forceinline__ float sigmoidf_(float x){ return 1.f/(1.f+expf(-x)); }
__device__ __forceinline__ float softplusf_(float x){ return fmaxf(x,0.f)+log1pf(expf(-fabsf(x))); }
__device__ __forceinline__ float tf32r_(float x){
    uint32_t u; asm("cvt.rna.tf32.f32 %0, %1;" : "=r"(u) : "f"(x));
    return __uint_as_float(u);
}
__device__ __forceinline__ void mma_tf32_(float4& d,
    uint32_t a0, uint32_t a1, uint32_t a2, uint32_t a3,
    uint32_t b0, uint32_t b1)
{
    asm volatile("mma.sync.aligned.m16n8k8.row.col.f32.tf32.tf32.f32 "
        "{%0,%1,%2,%3}, {%4,%5,%6,%7}, {%8,%9}, {%0,%1,%2,%3};\n"
        : "+f"(d.x), "+f"(d.y), "+f"(d.z), "+f"(d.w)
        : "r"(a0), "r"(a1), "r"(a2), "r"(a3), "r"(b0), "r"(b1));
}

// ---------------- TF32 tensor-core GEMM: C = A(M,K; lda) * W(N,K)^T ----------------
__global__ __launch_bounds__(256, 2)
void tgemm(const float* __restrict__ A, int lda,
           const float* __restrict__ W,
           float* __restrict__ C, int ldc,
           int M, int Nn, int K, int ep,
           const float* __restrict__ bias,
           const float* __restrict__ aux,
           const float* __restrict__ alpha_p)
{
    __shared__ float As[32*LDS_];   // [k][m]
    __shared__ float Ws[32*LDS_];   // [k][n]

    const int tid = threadIdx.x;
    const int bm = blockIdx.y * 128;
    const int bn = blockIdx.x * 128;
    const int warp = tid >> 5, lane = tid & 31;
    const int g = lane >> 2, tig = lane & 3;
    const int wm = (warp >> 2) * 64;
    const int wn = (warp & 3) * 32;

    const int lr = tid >> 1;
    const int lk = (tid & 1) * 16;
    const float* Ap = A + (size_t)(bm + lr) * lda + lk;
    const float* Wp = W + (size_t)(bn + lr) * K + lk;
    const bool wvalid = (bn + lr) < Nn;

    float4 acc[4][4];
    #pragma unroll
    for (int i = 0; i < 4; i++)
        #pragma unroll
        for (int j = 0; j < 4; j++) acc[i][j] = make_float4(0.f,0.f,0.f,0.f);

    float4 ra[4], rw[4];
    #pragma unroll
    for (int q = 0; q < 4; q++) {
        ra[q] = *(const float4*)(Ap + q*4);
        rw[q] = wvalid ? *(const float4*)(Wp + q*4) : make_float4(0.f,0.f,0.f,0.f);
    }

    for (int kt = 0; kt < K; kt += 32) {
        __syncthreads();
        #pragma unroll
        for (int q = 0; q < 4; q++) {
            int kk = lk + q*4;
            As[(kk+0)*LDS_ + lr] = tf32r_(ra[q].x);
            As[(kk+1)*LDS_ + lr] = tf32r_(ra[q].y);
            As[(kk+2)*LDS_ + lr] = tf32r_(ra[q].z);
            As[(kk+3)*LDS_ + lr] = tf32r_(ra[q].w);
            Ws[(kk+0)*LDS_ + lr] = tf32r_(rw[q].x);
            Ws[(kk+1)*LDS_ + lr] = tf32r_(rw[q].y);
            Ws[(kk+2)*LDS_ + lr] = tf32r_(rw[q].z);
            Ws[(kk+3)*LDS_ + lr] = tf32r_(rw[q].w);
        }
        __syncthreads();

        if (kt + 32 < K) {
            const float* Ap2 = Ap + kt + 32;
            const float* Wp2 = Wp + kt + 32;
            #pragma unroll
            for (int q = 0; q < 4; q++) {
                ra[q] = *(const float4*)(Ap2 + q*4);
                rw[q] = wvalid ? *(const float4*)(Wp2 + q*4) : make_float4(0.f,0.f,0.f,0.f);
            }
        }

        #pragma unroll
        for (int k0 = 0; k0 < 32; k0 += 8) {
            uint32_t af[4][4], bf[4][2];
            const float* a_r0 = &As[(k0+tig  )*LDS_ + wm + g];
            const float* a_r1 = &As[(k0+tig+4)*LDS_ + wm + g];
            #pragma unroll
            for (int mt = 0; mt < 4; mt++) {
                af[mt][0] = __float_as_uint(a_r0[mt*16    ]);
                af[mt][1] = __float_as_uint(a_r0[mt*16 + 8]);
                af[mt][2] = __float_as_uint(a_r1[mt*16    ]);
                af[mt][3] = __float_as_uint(a_r1[mt*16 + 8]);
            }
            const float* b_r0 = &Ws[(k0+tig  )*LDS_ + wn + g];
            const float* b_r1 = &Ws[(k0+tig+4)*LDS_ + wn + g];
            #pragma unroll
            for (int nt = 0; nt < 4; nt++) {
                bf[nt][0] = __float_as_uint(b_r0[nt*8]);
                bf[nt][1] = __float_as_uint(b_r1[nt*8]);
            }
            #pragma unroll
            for (int mt = 0; mt < 4; mt++)
                #pragma unroll
                for (int nt = 0; nt < 4; nt++)
                    mma_tf32_(acc[mt][nt], af[mt][0], af[mt][1], af[mt][2], af[mt][3],
                              bf[nt][0], bf[nt][1]);
        }
    }

    float alpha = 0.f;
    if (ep == 2) alpha = sigmoidf_(alpha_p[0]);

    #pragma unroll
    for (int mt = 0; mt < 4; mt++) {
        int r0 = bm + wm + mt*16 + g;
        #pragma unroll
        for (int nt = 0; nt < 4; nt++) {
            int c0 = bn + wn + nt*8 + 2*tig;
            if (c0 < Nn) {
                float v0 = acc[mt][nt].x, v1 = acc[mt][nt].y;
                float v2 = acc[mt][nt].z, v3 = acc[mt][nt].w;
                if (ep == 1) {
                    float b0v = bias[c0], b1v = bias[c0+1];
                    v0 = softplusf_(v0 + b0v); v1 = softplusf_(v1 + b1v);
                    v2 = softplusf_(v2 + b0v); v3 = softplusf_(v3 + b1v);
                } else if (ep == 2) {
                    size_t o0 = (size_t)r0*ldc + c0, o1 = (size_t)(r0+8)*ldc + c0;
                    v0 = alpha*aux[o0]   + (1.f-alpha)*v0;
                    v1 = alpha*aux[o0+1] + (1.f-alpha)*v1;
                    v2 = alpha*aux[o1]   + (1.f-alpha)*v2;
                    v3 = alpha*aux[o1+1] + (1.f-alpha)*v3;
                }
                *(float2*)(C + (size_t)r0*ldc + c0)     = make_float2(v0, v1);
                *(float2*)(C + (size_t)(r0+8)*ldc + c0) = make_float2(v2, v3);
            }
        }
    }
}

// ---------------- RoPE tables (fp64 for accuracy) ----------------
__global__ void rope_init_k()
{
    int idx = blockIdx.x*256 + threadIdx.x;
    if (idx >= S_*32) return;
    int s = idx >> 5, d = idx & 31;
    double inv = exp(-((double)(2*d)/64.0) * log(10000.0));
    double a = (double)s * inv;
    g_rcos[idx] = (float)cos(a);
    g_rsin[idx] = (float)sin(a);
}

// ---------------- RMSNorm + RoPE (+q_gain) ----------------
__global__ __launch_bounds__(256)
void qk_norm_rope_k(const float* __restrict__ q_gain)
{
    int task = blockIdx.x*8 + (threadIdx.x >> 5);
    int lane = threadIdx.x & 31;
    int m = task / 20, hh = task % 20;
    int s = m & (S_-1);

    const float* src; float* dst;
    if (hh < 16) { src = g_qh + (size_t)m*DIM_ + hh*64; dst = g_qn + (size_t)m*DIM_ + hh*64; }
    else         { src = g_kv + (size_t)m*512 + (hh-16)*64; dst = g_kn + (size_t)m*256 + (hh-16)*64; }

    float v0 = src[lane], v1 = src[lane+32];
    float ss = v0*v0 + v1*v1;
    #pragma unroll
    for (int off = 16; off >= 1; off >>= 1) ss += __shfl_xor_sync(0xffffffffu, ss, off);
    float r = rsqrtf(ss/64.f + EPSF);
    v0 *= r; v1 *= r;
    float c  = g_rcos[s*32 + lane];
    float sn = g_rsin[s*32 + lane];
    float o0 =  v0*c + v1*sn;
    float o1 = -v0*sn + v1*c;
    if (hh < 16) { float g = q_gain[hh]; o0 *= g; o1 *= g; }
    dst[lane] = o0; dst[lane+32] = o1;
}

// ---------------- TF32 tensor-core causal flash attention ----------------
// Q tile 128 (8 warps x 16 rows), K tile 64. smem: Ks/Vs row-major [c][d] (stride 68),
// Ps [m][c] (stride 68). Dynamic smem.
#define FA_KS 0
#define FA_VS (64*68)
#define FA_PS (2*64*68)
#define FA_SMEM ((2*64*68 + 128*68)*4)

__global__ __launch_bounds__(256, 2)
void flash_attn_tc()
{
    extern __shared__ float sm[];
    float* Ks = sm + FA_KS;
    float* Vs = sm + FA_VS;
    float* Ps = sm + FA_PS;

    const int tid = threadIdx.x;
    const int warp = tid >> 5, lane = tid & 31;
    const int g = lane >> 2, tig = lane & 3;
    const int qx = blockIdx.x, h = blockIdx.y, b = blockIdx.z;
    const int kh = h >> 2;
    const int q0 = qx * 128;
    const int wrow = warp * 16;
    const int r0g = q0 + wrow + g, r1g = r0g + 8;

    // persistent Q fragments (tf32)
    uint32_t qf[8][4];
    {
        const float* Qb = g_qn + ((size_t)(b*S_ + q0 + wrow))*DIM_ + h*64;
        #pragma unroll
        for (int ch = 0; ch < 8; ch++) {
            qf[ch][0] = __float_as_uint(tf32r_(Qb[(size_t)(g  )*DIM_ + ch*8 + tig    ]));
            qf[ch][1] = __float_as_uint(tf32r_(Qb[(size_t)(g+8)*DIM_ + ch*8 + tig    ]));
            qf[ch][2] = __float_as_uint(tf32r_(Qb[(size_t)(g  )*DIM_ + ch*8 + tig + 4]));
            qf[ch][3] = __float_as_uint(tf32r_(Qb[(size_t)(g+8)*DIM_ + ch*8 + tig + 4]));
        }
    }

    float4 of[8];
    #pragma unroll
    for (int nb = 0; nb < 8; nb++) of[nb] = make_float4(0.f,0.f,0.f,0.f);
    float m0 = -1e30f, m1 = -1e30f, l0 = 0.f, l1 = 0.f;

    const int KT = 2*qx + 2;
    const int cld = tid >> 2;               // loader row 0..63
    const int cbd = (tid & 3) * 16;         // loader col base

    for (int kt = 0; kt < KT; kt++) {
        __syncthreads();
        {
            size_t krow = (size_t)(b*S_ + kt*64 + cld);
            const float* kp = g_kn + krow*256 + kh*64 + cbd;
            const float* vp = g_kv + krow*512 + 256 + kh*64 + cbd;
            #pragma unroll
            for (int j = 0; j < 4; j++) {
                float4 k4 = *(const float4*)(kp + 4*j);
                float4 v4 = *(const float4*)(vp + 4*j);
                k4.x=tf32r_(k4.x); k4.y=tf32r_(k4.y); k4.z=tf32r_(k4.z); k4.w=tf32r_(k4.w);
                v4.x=tf32r_(v4.x); v4.y=tf32r_(v4.y); v4.z=tf32r_(v4.z); v4.w=tf32r_(v4.w);
                *(float4*)&Ks[cld*68 + cbd + 4*j] = k4;
                *(float4*)&Vs[cld*68 + cbd + 4*j] = v4;
            }
        }
        __syncthreads();

        const int ktb = kt*64;
        if (ktb <= q0 + wrow + 15) {      // warp has at least one unmasked row
            // ---- S = Q K^T ----
            float4 sc[8];
            #pragma unroll
            for (int nb = 0; nb < 8; nb++) sc[nb] = make_float4(0.f,0.f,0.f,0.f);
            #pragma unroll
            for (int ch = 0; ch < 8; ch++) {
                const int k0 = ch*8;
                #pragma unroll
                for (int nb = 0; nb < 8; nb++) {
                    uint32_t b0 = __float_as_uint(Ks[(nb*8+g)*68 + k0 + tig    ]);
                    uint32_t b1 = __float_as_uint(Ks[(nb*8+g)*68 + k0 + tig + 4]);
                    mma_tf32_(sc[nb], qf[ch][0], qf[ch][1], qf[ch][2], qf[ch][3], b0, b1);
                }
            }
            // scale + mask
            const bool needmask = (ktb + 63) > r0g;   // any column may exceed rows
            #pragma unroll
            for (int nb = 0; nb < 8; nb++) {
                sc[nb].x *= 0.125f; sc[nb].y *= 0.125f; sc[nb].z *= 0.125f; sc[nb].w *= 0.125f;
                if (needmask) {
                    int c0 = ktb + nb*8 + 2*tig, c1 = c0 + 1;
                    if (c0 > r0g) sc[nb].x = -1e30f;
                    if (c1 > r0g) sc[nb].y = -1e30f;
                    if (c0 > r1g) sc[nb].z = -1e30f;
                    if (c1 > r1g) sc[nb].w = -1e30f;
                }
            }
            // ---- online softmax ----
            float rm0 = -1e30f, rm1 = -1e30f;
            #pragma unroll
            for (int nb = 0; nb < 8; nb++) {
                rm0 = fmaxf(rm0, fmaxf(sc[nb].x, sc[nb].y));
                rm1 = fmaxf(rm1, fmaxf(sc[nb].z, sc[nb].w));
            }
            rm0 = fmaxf(rm0, __shfl_xor_sync(0xffffffffu, rm0, 1));
            rm0 = fmaxf(rm0, __shfl_xor_sync(0xffffffffu, rm0, 2));
            rm1 = fmaxf(rm1, __shfl_xor_sync(0xffffffffu, rm1, 1));
            rm1 = fmaxf(rm1, __shfl_xor_sync(0xffffffffu, rm1, 2));
            float nm0 = fmaxf(m0, rm0), nm1 = fmaxf(m1, rm1);
            float corr0 = __expf(m0 - nm0), corr1 = __expf(m1 - nm1);
            float rs0 = 0.f, rs1 = 0.f;
            #pragma unroll
            for (int nb = 0; nb < 8; nb++) {
                sc[nb].x = __expf(sc[nb].x - nm0);
                sc[nb].y = __expf(sc[nb].y - nm0);
                sc[nb].z = __expf(sc[nb].z - nm1);
                sc[nb].w = __expf(sc[nb].w - nm1);
                rs0 += sc[nb].x + sc[nb].y;
                rs1 += sc[nb].z + sc[nb].w;
            }
            rs0 += __shfl_xor_sync(0xffffffffu, rs0, 1);
            rs0 += __shfl_xor_sync(0xffffffffu, rs0, 2);
            rs1 += __shfl_xor_sync(0xffffffffu, rs1, 1);
            rs1 += __shfl_xor_sync(0xffffffffu, rs1, 2);
            l0 = l0*corr0 + rs0; l1 = l1*corr1 + rs1;
            m0 = nm0; m1 = nm1;
            #pragma unroll
            for (int nb = 0; nb < 8; nb++) {
                of[nb].x *= corr0; of[nb].y *= corr0;
                of[nb].z *= corr1; of[nb].w *= corr1;
            }
            // ---- P -> smem (warp-private rows), tf32 rounded ----
            #pragma unroll
            for (int nb = 0; nb < 8; nb++) {
                *(float2*)&Ps[(wrow+g  )*68 + nb*8 + 2*tig] =
                    make_float2(tf32r_(sc[nb].x), tf32r_(sc[nb].y));
                *(float2*)&Ps[(wrow+g+8)*68 + nb*8 + 2*tig] =
                    make_float2(tf32r_(sc[nb].z), tf32r_(sc[nb].w));
            }
            __syncwarp();
            // ---- O += P V ----
            #pragma unroll
            for (int ch = 0; ch < 8; ch++) {
                const int kc = ch*8;
                uint32_t a0 = __float_as_uint(Ps[(wrow+g  )*68 + kc + tig    ]);
                uint32_t a1 = __float_as_uint(Ps[(wrow+g+8)*68 + kc + tig    ]);
                uint32_t a2 = __float_as_uint(Ps[(wrow+g  )*68 + kc + tig + 4]);
                uint32_t a3 = __float_as_uint(Ps[(wrow+g+8)*68 + kc + tig + 4]);
                #pragma unroll
                for (int nb = 0; nb < 8; nb++) {
                    uint32_t b0 = __float_as_uint(Vs[(kc+tig  )*68 + nb*8 + g]);
                    uint32_t b1 = __float_as_uint(Vs[(kc+tig+4)*68 + nb*8 + g]);
                    mma_tf32_(of[nb], a0, a1, a2, a3, b0, b1);
                }
            }
        }
    }

    // ---- normalize + store ----
    float inv0 = 1.f / l0, inv1 = 1.f / l1;
    float* O0 = g_attn + (size_t)(b*S_ + r0g)*DIM_ + h*64;
    float* O1 = g_attn + (size_t)(b*S_ + r1g)*DIM_ + h*64;
    #pragma unroll
    for (int nb = 0; nb < 8; nb++) {
        *(float2*)(O0 + nb*8 + 2*tig) = make_float2(of[nb].x*inv0, of[nb].y*inv0);
        *(float2*)(O1 + nb*8 + 2*tig) = make_float2(of[nb].z*inv1, of[nb].w*inv1);
    }
}

// ---------------- depthwise causal conv (K=4) + SiLU ----------------
__global__ __launch_bounds__(256)
void conv_silu_k(const float* __restrict__ conv_w, const float* __restrict__ conv_b)
{
    int idx = blockIdx.x*256 + threadIdx.x;
    int m = idx >> 11, i = idx & (I_-1);
    int b = m >> 11, s = m & (S_-1);
    float acc = conv_b[i];
    #pragma unroll
    for (int k = 0; k < K_; k++) {
        int sp = s - 3 + k;
        if (sp >= 0) acc += g_mp[((size_t)(b*S_ + sp))*(2*I_) + i] * conv_w[i*K_ + k];
    }
    g_u[idx] = acc * sigmoidf_(acc);
}

// ---------------- SSM sequential scan, fused D/gate epilogue ----------------
__global__ __launch_bounds__(256)
void ssm_scan_k(const float* __restrict__ A_log, const float* __restrict__ Dvec)
{
    int gtid = blockIdx.x*256 + threadIdx.x;
    int grp = gtid >> 4, n = gtid & 15;
    int b = grp >> 11, i = grp & (I_-1);

    float A  = -expf(A_log[i*N_ + n]);
    float Dv = Dvec[i];
    float state = 0.f;
    size_t base = (size_t)b * S_;

    for (int t = 0; t < S_; t++) {
        size_t m = base + t;
        float d  = g_delta[m*I_ + i];
        float uu = g_u[m*I_ + i];
        float Bv = g_params[m*96 + 64 + n];
        float Cv = g_params[m*96 + 80 + n];
        state = state*expf(d*A) + d*Bv*uu;
        float yv = state*Cv;
        #pragma unroll
        for (int off = 8; off >= 1; off >>= 1) yv += __shfl_xor_sync(0xffffffffu, yv, off);
        if (n == 0) {
            float g = g_mp[m*(2*I_) + I_ + i];
            g_y[m*I_ + i] = (yv + uu*Dv) * g * sigmoidf_(g);
        }
    }
}

// ---------------- launcher ----------------
extern "C" void kernel_launch(void* const* d_in, const int* in_sizes, int n_in,
                              void* d_out, int out_size)
{
    const float* x        = (const float*)d_in[0];
    const float* W_mamba  = (const float*)d_in[1];
    const float* W_q      = (const float*)d_in[2];
    const float* W_kv     = (const float*)d_in[3];
    const float* q_gain   = (const float*)d_in[4];
    const float* conv_w   = (const float*)d_in[5];
    const float* conv_b   = (const float*)d_in[6];
    const float* W_xproj  = (const float*)d_in[7];
    const float* W_dt     = (const float*)d_in[8];
    const float* b_dt     = (const float*)d_in[9];
    const float* A_log    = (const float*)d_in[10];
    const float* Dvec     = (const float*)d_in[11];
    const float* W_mout   = (const float*)d_in[12];
    const float* W_proj   = (const float*)d_in[13];
    const float* m_alpha  = (const float*)d_in[14];
    float* out = (float*)d_out;

    float *p_mp, *p_qh, *p_kv, *p_attn, *p_u, *p_params, *p_delta, *p_y, *p_merged;
    cudaGetSymbolAddress((void**)&p_mp, g_mp);
    cudaGetSymbolAddress((void**)&p_qh, g_qh);
    cudaGetSymbolAddress((void**)&p_kv, g_kv);
    cudaGetSymbolAddress((void**)&p_attn, g_attn);
    cudaGetSymbolAddress((void**)&p_u, g_u);
    cudaGetSymbolAddress((void**)&p_params, g_params);
    cudaGetSymbolAddress((void**)&p_delta, g_delta);
    cudaGetSymbolAddress((void**)&p_y, g_y);
    cudaGetSymbolAddress((void**)&p_merged, g_merged);

    cudaFuncSetAttribute(flash_attn_tc, cudaFuncAttributeMaxDynamicSharedMemorySize, FA_SMEM);

    // 0. rope tables
    rope_init_k<<<(S_*32 + 255)/256, 256>>>();

    // 1. mp = x @ W_mamba.T
    tgemm<<<dim3(32,32), 256>>>(x, DIM_, W_mamba, p_mp, 2*I_, MTOT, 2*I_, DIM_, 0, nullptr, nullptr, nullptr);
    // 2. q = x @ W_q.T
    tgemm<<<dim3(8,32), 256>>>(x, DIM_, W_q, p_qh, DIM_, MTOT, DIM_, DIM_, 0, nullptr, nullptr, nullptr);
    // 3. kv = x @ W_kv.T
    tgemm<<<dim3(4,32), 256>>>(x, DIM_, W_kv, p_kv, 512, MTOT, 512, DIM_, 0, nullptr, nullptr, nullptr);

    // 4. rmsnorm + rope
    qk_norm_rope_k<<<(MTOT*20)/8, 256>>>(q_gain);

    // 5. causal GQA attention (tensor cores)
    flash_attn_tc<<<dim3(S_/128, H_, B_), 256, FA_SMEM>>>();

    // 6. conv + silu
    conv_silu_k<<<(MTOT*I_)/256, 256>>>(conv_w, conv_b);

    // 7. params = u @ W_xproj.T
    tgemm<<<dim3(1,32), 256>>>(p_u, I_, W_xproj, p_params, 96, MTOT, 96, I_, 0, nullptr, nullptr, nullptr);

    // 8. delta = softplus(dt_low @ W_dt.T + b_dt)
    tgemm<<<dim3(16,32), 256>>>(p_params, 96, W_dt, p_delta, I_, MTOT, I_, DTR_, 1, b_dt, nullptr, nullptr);

    // 9. scan (+ D skip + gate)
    ssm_scan_k<<<(B_*I_*N_)/256, 256>>>(A_log, Dvec);

    // 10. merged = alpha*attn + (1-alpha) * (y @ W_mamba_out.T)
    tgemm<<<dim3(8,32), 256>>>(p_y, I_, W_mout, p_merged, DIM_, MTOT, DIM_, I_, 2, nullptr, p_attn, m_alpha);

    // 11. out = merged @ W_proj.T
    tgemm<<<dim3(8,32), 256>>>(p_merged, DIM_, W_proj, out, DIM_, MTOT, DIM_, DIM_, 0, nullptr, nullptr, nullptr);
}

// round 5
// speedup vs baseline: 1.5994x; 1.0519x over previous
#include <cuda_runtime.h>
#include <math.h>
#include <stdint.h>

// ---------------- problem constants ----------------
#define B_   2
#define S_   2048
#define DIM_ 1024
#define H_   16
#define KVH_ 4
#define HD_  64
#define I_   2048
#define N_   16
#define DTR_ 64
#define K_   4
#define MTOT (B_*S_)          // 4096
#define EPSF 1.1920929e-07f
#define LDS_ 136              // gemm smem row stride

// ---------------- scratch (static device, no allocs) ----------------
__device__ float g_mp[MTOT*(size_t)(2*I_)];      // x @ W_mamba.T  (4096 x 4096)
__device__ float g_qh[MTOT*(size_t)DIM_];        // x @ W_q.T
__device__ float g_kv[MTOT*(size_t)(2*KVH_*HD_)];// x @ W_kv.T (k|v)
__device__ float g_qn[MTOT*(size_t)DIM_];        // normed+roped q
__device__ float g_kn[MTOT*(size_t)(KVH_*HD_)];  // normed+roped k
__device__ float g_attn[MTOT*(size_t)DIM_];      // attention out
__device__ float g_u[MTOT*(size_t)I_];           // conv+silu
__device__ float g_params[MTOT*(size_t)96];      // xproj out
__device__ float g_delta[MTOT*(size_t)I_];       // softplus(dt)
__device__ float g_y[MTOT*(size_t)I_];           // scan out (gated)
__device__ float g_merged[MTOT*(size_t)DIM_];    // alpha-merged
__device__ float g_rcos[S_*32];
__device__ float g_rsin[S_*32];

// ---------------- helpers ----------------
__device__ __forceinline__ float sigmoidf_(float x){ return 1.f/(1.f+expf(-x)); }
__device__ __forceinline__ float softplusf_(float x){ return fmaxf(x,0.f)+log1pf(expf(-fabsf(x))); }
__device__ __forceinline__ float tf32r_(float x){
    uint32_t u; asm("cvt.rna.tf32.f32 %0, %1;" : "=r"(u) : "f"(x));
    return __uint_as_float(u);
}
__device__ __forceinline__ void mma_tf32_(float4& d,
    uint32_t a0, uint32_t a1, uint32_t a2, uint32_t a3,
    uint32_t b0, uint32_t b1)
{
    asm volatile("mma.sync.aligned.m16n8k8.row.col.f32.tf32.tf32.f32 "
        "{%0,%1,%2,%3}, {%4,%5,%6,%7}, {%8,%9}, {%0,%1,%2,%3};\n"
        : "+f"(d.x), "+f"(d.y), "+f"(d.z), "+f"(d.w)
        : "r"(a0), "r"(a1), "r"(a2), "r"(a3), "r"(b0), "r"(b1));
}

// ---------------- TF32 tensor-core GEMM: C = A(M,K; lda) * W(N,K)^T ----------------
__global__ __launch_bounds__(256, 2)
void tgemm(const float* __restrict__ A, int lda,
           const float* __restrict__ W,
           float* __restrict__ C, int ldc,
           int M, int Nn, int K, int ep,
           const float* __restrict__ bias,
           const float* __restrict__ aux,
           const float* __restrict__ alpha_p)
{
    __shared__ float As[32*LDS_];   // [k][m]
    __shared__ float Ws[32*LDS_];   // [k][n]

    const int tid = threadIdx.x;
    const int bm = blockIdx.y * 128;
    const int bn = blockIdx.x * 128;
    const int warp = tid >> 5, lane = tid & 31;
    const int g = lane >> 2, tig = lane & 3;
    const int wm = (warp >> 2) * 64;
    const int wn = (warp & 3) * 32;

    const int lr = tid >> 1;
    const int lk = (tid & 1) * 16;
    const float* Ap = A + (size_t)(bm + lr) * lda + lk;
    const float* Wp = W + (size_t)(bn + lr) * K + lk;
    const bool wvalid = (bn + lr) < Nn;

    float4 acc[4][4];
    #pragma unroll
    for (int i = 0; i < 4; i++)
        #pragma unroll
        for (int j = 0; j < 4; j++) acc[i][j] = make_float4(0.f,0.f,0.f,0.f);

    float4 ra[4], rw[4];
    #pragma unroll
    for (int q = 0; q < 4; q++) {
        ra[q] = *(const float4*)(Ap + q*4);
        rw[q] = wvalid ? *(const float4*)(Wp + q*4) : make_float4(0.f,0.f,0.f,0.f);
    }

    for (int kt = 0; kt < K; kt += 32) {
        __syncthreads();
        #pragma unroll
        for (int q = 0; q < 4; q++) {
            int kk = lk + q*4;
            As[(kk+0)*LDS_ + lr] = tf32r_(ra[q].x);
            As[(kk+1)*LDS_ + lr] = tf32r_(ra[q].y);
            As[(kk+2)*LDS_ + lr] = tf32r_(ra[q].z);
            As[(kk+3)*LDS_ + lr] = tf32r_(ra[q].w);
            Ws[(kk+0)*LDS_ + lr] = tf32r_(rw[q].x);
            Ws[(kk+1)*LDS_ + lr] = tf32r_(rw[q].y);
            Ws[(kk+2)*LDS_ + lr] = tf32r_(rw[q].z);
            Ws[(kk+3)*LDS_ + lr] = tf32r_(rw[q].w);
        }
        __syncthreads();

        if (kt + 32 < K) {
            const float* Ap2 = Ap + kt + 32;
            const float* Wp2 = Wp + kt + 32;
            #pragma unroll
            for (int q = 0; q < 4; q++) {
                ra[q] = *(const float4*)(Ap2 + q*4);
                rw[q] = wvalid ? *(const float4*)(Wp2 + q*4) : make_float4(0.f,0.f,0.f,0.f);
            }
        }

        #pragma unroll
        for (int k0 = 0; k0 < 32; k0 += 8) {
            uint32_t af[4][4], bf[4][2];
            const float* a_r0 = &As[(k0+tig  )*LDS_ + wm + g];
            const float* a_r1 = &As[(k0+tig+4)*LDS_ + wm + g];
            #pragma unroll
            for (int mt = 0; mt < 4; mt++) {
                af[mt][0] = __float_as_uint(a_r0[mt*16    ]);
                af[mt][1] = __float_as_uint(a_r0[mt*16 + 8]);
                af[mt][2] = __float_as_uint(a_r1[mt*16    ]);
                af[mt][3] = __float_as_uint(a_r1[mt*16 + 8]);
            }
            const float* b_r0 = &Ws[(k0+tig  )*LDS_ + wn + g];
            const float* b_r1 = &Ws[(k0+tig+4)*LDS_ + wn + g];
            #pragma unroll
            for (int nt = 0; nt < 4; nt++) {
                bf[nt][0] = __float_as_uint(b_r0[nt*8]);
                bf[nt][1] = __float_as_uint(b_r1[nt*8]);
            }
            #pragma unroll
            for (int mt = 0; mt < 4; mt++)
                #pragma unroll
                for (int nt = 0; nt < 4; nt++)
                    mma_tf32_(acc[mt][nt], af[mt][0], af[mt][1], af[mt][2], af[mt][3],
                              bf[nt][0], bf[nt][1]);
        }
    }

    float alpha = 0.f;
    if (ep == 2) alpha = sigmoidf_(alpha_p[0]);

    #pragma unroll
    for (int mt = 0; mt < 4; mt++) {
        int r0 = bm + wm + mt*16 + g;
        #pragma unroll
        for (int nt = 0; nt < 4; nt++) {
            int c0 = bn + wn + nt*8 + 2*tig;
            if (c0 < Nn) {
                float v0 = acc[mt][nt].x, v1 = acc[mt][nt].y;
                float v2 = acc[mt][nt].z, v3 = acc[mt][nt].w;
                if (ep == 1) {
                    float b0v = bias[c0], b1v = bias[c0+1];
                    v0 = softplusf_(v0 + b0v); v1 = softplusf_(v1 + b1v);
                    v2 = softplusf_(v2 + b0v); v3 = softplusf_(v3 + b1v);
                } else if (ep == 2) {
                    size_t o0 = (size_t)r0*ldc + c0, o1 = (size_t)(r0+8)*ldc + c0;
                    v0 = alpha*aux[o0]   + (1.f-alpha)*v0;
                    v1 = alpha*aux[o0+1] + (1.f-alpha)*v1;
                    v2 = alpha*aux[o1]   + (1.f-alpha)*v2;
                    v3 = alpha*aux[o1+1] + (1.f-alpha)*v3;
                }
                *(float2*)(C + (size_t)r0*ldc + c0)     = make_float2(v0, v1);
                *(float2*)(C + (size_t)(r0+8)*ldc + c0) = make_float2(v2, v3);
            }
        }
    }
}

// ---------------- RoPE tables (fp64 for accuracy) ----------------
__global__ void rope_init_k()
{
    int idx = blockIdx.x*256 + threadIdx.x;
    if (idx >= S_*32) return;
    int s = idx >> 5, d = idx & 31;
    double inv = exp(-((double)(2*d)/64.0) * log(10000.0));
    double a = (double)s * inv;
    g_rcos[idx] = (float)cos(a);
    g_rsin[idx] = (float)sin(a);
}

// ---------------- RMSNorm + RoPE (+q_gain) ----------------
__global__ __launch_bounds__(256)
void qk_norm_rope_k(const float* __restrict__ q_gain)
{
    int task = blockIdx.x*8 + (threadIdx.x >> 5);
    int lane = threadIdx.x & 31;
    int m = task / 20, hh = task % 20;
    int s = m & (S_-1);

    const float* src; float* dst;
    if (hh < 16) { src = g_qh + (size_t)m*DIM_ + hh*64; dst = g_qn + (size_t)m*DIM_ + hh*64; }
    else         { src = g_kv + (size_t)m*512 + (hh-16)*64; dst = g_kn + (size_t)m*256 + (hh-16)*64; }

    float v0 = src[lane], v1 = src[lane+32];
    float ss = v0*v0 + v1*v1;
    #pragma unroll
    for (int off = 16; off >= 1; off >>= 1) ss += __shfl_xor_sync(0xffffffffu, ss, off);
    float r = rsqrtf(ss/64.f + EPSF);
    v0 *= r; v1 *= r;
    float c  = g_rcos[s*32 + lane];
    float sn = g_rsin[s*32 + lane];
    float o0 =  v0*c + v1*sn;
    float o1 = -v0*sn + v1*c;
    if (hh < 16) { float g = q_gain[hh]; o0 *= g; o1 *= g; }
    dst[lane] = o0; dst[lane+32] = o1;
}

// ---------------- TF32 tensor-core causal flash attention ----------------
// Q tile 128 (8 warps x 16 rows), K tile 64. smem: Ks/Vs row-major [c][d] (stride 68),
// Ps [m][c] (stride 68). Dynamic smem. NO min-blocks clause: avoid register spills.
#define FA_KS 0
#define FA_VS (64*68)
#define FA_PS (2*64*68)
#define FA_SMEM ((2*64*68 + 128*68)*4)

__global__ __launch_bounds__(256)
void flash_attn_tc()
{
    extern __shared__ float sm[];
    float* Ks = sm + FA_KS;
    float* Vs = sm + FA_VS;
    float* Ps = sm + FA_PS;

    const int tid = threadIdx.x;
    const int warp = tid >> 5, lane = tid & 31;
    const int g = lane >> 2, tig = lane & 3;
    const int qx = (gridDim.x - 1) - blockIdx.x;   // heavy tiles first
    const int h = blockIdx.y, b = blockIdx.z;
    const int kh = h >> 2;
    const int q0 = qx * 128;
    const int wrow = warp * 16;
    const int r0g = q0 + wrow + g, r1g = r0g + 8;

    // persistent Q fragments (tf32)
    uint32_t qf[8][4];
    {
        const float* Qb = g_qn + ((size_t)(b*S_ + q0 + wrow))*DIM_ + h*64;
        #pragma unroll
        for (int ch = 0; ch < 8; ch++) {
            qf[ch][0] = __float_as_uint(tf32r_(Qb[(size_t)(g  )*DIM_ + ch*8 + tig    ]));
            qf[ch][1] = __float_as_uint(tf32r_(Qb[(size_t)(g+8)*DIM_ + ch*8 + tig    ]));
            qf[ch][2] = __float_as_uint(tf32r_(Qb[(size_t)(g  )*DIM_ + ch*8 + tig + 4]));
            qf[ch][3] = __float_as_uint(tf32r_(Qb[(size_t)(g+8)*DIM_ + ch*8 + tig + 4]));
        }
    }

    float4 of[8];
    #pragma unroll
    for (int nb = 0; nb < 8; nb++) of[nb] = make_float4(0.f,0.f,0.f,0.f);
    float m0 = -1e30f, m1 = -1e30f, l0 = 0.f, l1 = 0.f;

    const int KT = 2*qx + 2;
    const int cld = tid >> 2;               // loader row 0..63
    const int cbd = (tid & 3) * 16;         // loader col base

    for (int kt = 0; kt < KT; kt++) {
        __syncthreads();
        {
            size_t krow = (size_t)(b*S_ + kt*64 + cld);
            const float* kp = g_kn + krow*256 + kh*64 + cbd;
            const float* vp = g_kv + krow*512 + 256 + kh*64 + cbd;
            #pragma unroll
            for (int j = 0; j < 4; j++) {
                float4 k4 = *(const float4*)(kp + 4*j);
                float4 v4 = *(const float4*)(vp + 4*j);
                k4.x=tf32r_(k4.x); k4.y=tf32r_(k4.y); k4.z=tf32r_(k4.z); k4.w=tf32r_(k4.w);
                v4.x=tf32r_(v4.x); v4.y=tf32r_(v4.y); v4.z=tf32r_(v4.z); v4.w=tf32r_(v4.w);
                *(float4*)&Ks[cld*68 + cbd + 4*j] = k4;
                *(float4*)&Vs[cld*68 + cbd + 4*j] = v4;
            }
        }
        __syncthreads();

        const int ktb = kt*64;
        if (ktb <= q0 + wrow + 15) {      // warp has at least one unmasked row
            // ---- S = Q K^T ----
            float4 sc[8];
            #pragma unroll
            for (int nb = 0; nb < 8; nb++) sc[nb] = make_float4(0.f,0.f,0.f,0.f);
            #pragma unroll
            for (int ch = 0; ch < 8; ch++) {
                const int k0 = ch*8;
                #pragma unroll
                for (int nb = 0; nb < 8; nb++) {
                    uint32_t b0 = __float_as_uint(Ks[(nb*8+g)*68 + k0 + tig    ]);
                    uint32_t b1 = __float_as_uint(Ks[(nb*8+g)*68 + k0 + tig + 4]);
                    mma_tf32_(sc[nb], qf[ch][0], qf[ch][1], qf[ch][2], qf[ch][3], b0, b1);
                }
            }
            // scale + mask
            const bool needmask = (ktb + 63) > r0g;
            #pragma unroll
            for (int nb = 0; nb < 8; nb++) {
                sc[nb].x *= 0.125f; sc[nb].y *= 0.125f; sc[nb].z *= 0.125f; sc[nb].w *= 0.125f;
                if (needmask) {
                    int c0 = ktb + nb*8 + 2*tig, c1 = c0 + 1;
                    if (c0 > r0g) sc[nb].x = -1e30f;
                    if (c1 > r0g) sc[nb].y = -1e30f;
                    if (c0 > r1g) sc[nb].z = -1e30f;
                    if (c1 > r1g) sc[nb].w = -1e30f;
                }
            }
            // ---- online softmax ----
            float rm0 = -1e30f, rm1 = -1e30f;
            #pragma unroll
            for (int nb = 0; nb < 8; nb++) {
                rm0 = fmaxf(rm0, fmaxf(sc[nb].x, sc[nb].y));
                rm1 = fmaxf(rm1, fmaxf(sc[nb].z, sc[nb].w));
            }
            rm0 = fmaxf(rm0, __shfl_xor_sync(0xffffffffu, rm0, 1));
            rm0 = fmaxf(rm0, __shfl_xor_sync(0xffffffffu, rm0, 2));
            rm1 = fmaxf(rm1, __shfl_xor_sync(0xffffffffu, rm1, 1));
            rm1 = fmaxf(rm1, __shfl_xor_sync(0xffffffffu, rm1, 2));
            float nm0 = fmaxf(m0, rm0), nm1 = fmaxf(m1, rm1);
            float corr0 = __expf(m0 - nm0), corr1 = __expf(m1 - nm1);
            float rs0 = 0.f, rs1 = 0.f;
            #pragma unroll
            for (int nb = 0; nb < 8; nb++) {
                sc[nb].x = __expf(sc[nb].x - nm0);
                sc[nb].y = __expf(sc[nb].y - nm0);
                sc[nb].z = __expf(sc[nb].z - nm1);
                sc[nb].w = __expf(sc[nb].w - nm1);
                rs0 += sc[nb].x + sc[nb].y;
                rs1 += sc[nb].z + sc[nb].w;
            }
            rs0 += __shfl_xor_sync(0xffffffffu, rs0, 1);
            rs0 += __shfl_xor_sync(0xffffffffu, rs0, 2);
            rs1 += __shfl_xor_sync(0xffffffffu, rs1, 1);
            rs1 += __shfl_xor_sync(0xffffffffu, rs1, 2);
            l0 = l0*corr0 + rs0; l1 = l1*corr1 + rs1;
            m0 = nm0; m1 = nm1;
            #pragma unroll
            for (int nb = 0; nb < 8; nb++) {
                of[nb].x *= corr0; of[nb].y *= corr0;
                of[nb].z *= corr1; of[nb].w *= corr1;
            }
            // ---- P -> smem (warp-private rows), tf32 rounded ----
            #pragma unroll
            for (int nb = 0; nb < 8; nb++) {
                *(float2*)&Ps[(wrow+g  )*68 + nb*8 + 2*tig] =
                    make_float2(tf32r_(sc[nb].x), tf32r_(sc[nb].y));
                *(float2*)&Ps[(wrow+g+8)*68 + nb*8 + 2*tig] =
                    make_float2(tf32r_(sc[nb].z), tf32r_(sc[nb].w));
            }
            __syncwarp();
            // ---- O += P V ----
            #pragma unroll
            for (int ch = 0; ch < 8; ch++) {
                const int kc = ch*8;
                uint32_t a0 = __float_as_uint(Ps[(wrow+g  )*68 + kc + tig    ]);
                uint32_t a1 = __float_as_uint(Ps[(wrow+g+8)*68 + kc + tig    ]);
                uint32_t a2 = __float_as_uint(Ps[(wrow+g  )*68 + kc + tig + 4]);
                uint32_t a3 = __float_as_uint(Ps[(wrow+g+8)*68 + kc + tig + 4]);
                #pragma unroll
                for (int nb = 0; nb < 8; nb++) {
                    uint32_t b0 = __float_as_uint(Vs[(kc+tig  )*68 + nb*8 + g]);
                    uint32_t b1 = __float_as_uint(Vs[(kc+tig+4)*68 + nb*8 + g]);
                    mma_tf32_(of[nb], a0, a1, a2, a3, b0, b1);
                }
            }
        }
    }

    // ---- normalize + store ----
    float inv0 = 1.f / l0, inv1 = 1.f / l1;
    float* O0 = g_attn + (size_t)(b*S_ + r0g)*DIM_ + h*64;
    float* O1 = g_attn + (size_t)(b*S_ + r1g)*DIM_ + h*64;
    #pragma unroll
    for (int nb = 0; nb < 8; nb++) {
        *(float2*)(O0 + nb*8 + 2*tig) = make_float2(of[nb].x*inv0, of[nb].y*inv0);
        *(float2*)(O1 + nb*8 + 2*tig) = make_float2(of[nb].z*inv1, of[nb].w*inv1);
    }
}

// ---------------- depthwise causal conv (K=4) + SiLU ----------------
__global__ __launch_bounds__(256)
void conv_silu_k(const float* __restrict__ conv_w, const float* __restrict__ conv_b)
{
    int idx = blockIdx.x*256 + threadIdx.x;
    int m = idx >> 11, i = idx & (I_-1);
    int b = m >> 11, s = m & (S_-1);
    float acc = conv_b[i];
    #pragma unroll
    for (int k = 0; k < K_; k++) {
        int sp = s - 3 + k;
        if (sp >= 0) acc += g_mp[((size_t)(b*S_ + sp))*(2*I_) + i] * conv_w[i*K_ + k];
    }
    g_u[idx] = acc * sigmoidf_(acc);
}

// ---------------- SSM sequential scan, fused D/gate epilogue ----------------
__global__ __launch_bounds__(256)
void ssm_scan_k(const float* __restrict__ A_log, const float* __restrict__ Dvec)
{
    int gtid = blockIdx.x*256 + threadIdx.x;
    int grp = gtid >> 4, n = gtid & 15;
    int b = grp >> 11, i = grp & (I_-1);

    float A  = -expf(A_log[i*N_ + n]);
    float Dv = Dvec[i];
    float state = 0.f;
    size_t base = (size_t)b * S_;

    for (int t = 0; t < S_; t++) {
        size_t m = base + t;
        float d  = g_delta[m*I_ + i];
        float uu = g_u[m*I_ + i];
        float Bv = g_params[m*96 + 64 + n];
        float Cv = g_params[m*96 + 80 + n];
        state = state*expf(d*A) + d*Bv*uu;
        float yv = state*Cv;
        #pragma unroll
        for (int off = 8; off >= 1; off >>= 1) yv += __shfl_xor_sync(0xffffffffu, yv, off);
        if (n == 0) {
            float g = g_mp[m*(2*I_) + I_ + i];
            g_y[m*I_ + i] = (yv + uu*Dv) * g * sigmoidf_(g);
        }
    }
}

// ---------------- launcher (stream fork/join for branch concurrency) ----------------
extern "C" void kernel_launch(void* const* d_in, const int* in_sizes, int n_in,
                              void* d_out, int out_size)
{
    const float* x        = (const float*)d_in[0];
    const float* W_mamba  = (const float*)d_in[1];
    const float* W_q      = (const float*)d_in[2];
    const float* W_kv     = (const float*)d_in[3];
    const float* q_gain   = (const float*)d_in[4];
    const float* conv_w   = (const float*)d_in[5];
    const float* conv_b   = (const float*)d_in[6];
    const float* W_xproj  = (const float*)d_in[7];
    const float* W_dt     = (const float*)d_in[8];
    const float* b_dt     = (const float*)d_in[9];
    const float* A_log    = (const float*)d_in[10];
    const float* Dvec     = (const float*)d_in[11];
    const float* W_mout   = (const float*)d_in[12];
    const float* W_proj   = (const float*)d_in[13];
    const float* m_alpha  = (const float*)d_in[14];
    float* out = (float*)d_out;

    float *p_mp, *p_qh, *p_kv, *p_attn, *p_u, *p_params, *p_delta, *p_y, *p_merged;
    cudaGetSymbolAddress((void**)&p_mp, g_mp);
    cudaGetSymbolAddress((void**)&p_qh, g_qh);
    cudaGetSymbolAddress((void**)&p_kv, g_kv);
    cudaGetSymbolAddress((void**)&p_attn, g_attn);
    cudaGetSymbolAddress((void**)&p_u, g_u);
    cudaGetSymbolAddress((void**)&p_params, g_params);
    cudaGetSymbolAddress((void**)&p_delta, g_delta);
    cudaGetSymbolAddress((void**)&p_y, g_y);
    cudaGetSymbolAddress((void**)&p_merged, g_merged);

    cudaFuncSetAttribute(flash_attn_tc, cudaFuncAttributeMaxDynamicSharedMemorySize, FA_SMEM);

    // side stream + fork/join events (created per call; kernel_launch only runs
    // for correctness + capture, replays use the graph — no per-replay cost)
    cudaStream_t s1;
    cudaStreamCreate(&s1);
    cudaEvent_t e_fork, e_join;
    cudaEventCreateWithFlags(&e_fork, cudaEventDisableTiming);
    cudaEventCreateWithFlags(&e_join, cudaEventDisableTiming);

    // fork: side stream joins the capture
    cudaEventRecord(e_fork, 0);
    cudaStreamWaitEvent(s1, e_fork, 0);

    // ---- side branch (attention path) on s1 ----
    rope_init_k<<<(S_*32 + 255)/256, 256, 0, s1>>>();
    tgemm<<<dim3(8,32), 256, 0, s1>>>(x, DIM_, W_q, p_qh, DIM_, MTOT, DIM_, DIM_, 0, nullptr, nullptr, nullptr);
    tgemm<<<dim3(4,32), 256, 0, s1>>>(x, DIM_, W_kv, p_kv, 512, MTOT, 512, DIM_, 0, nullptr, nullptr, nullptr);
    qk_norm_rope_k<<<(MTOT*20)/8, 256, 0, s1>>>(q_gain);
    flash_attn_tc<<<dim3(S_/128, H_, B_), 256, FA_SMEM, s1>>>();
    cudaEventRecord(e_join, s1);

    // ---- main branch (mamba path) on default stream ----
    tgemm<<<dim3(32,32), 256>>>(x, DIM_, W_mamba, p_mp, 2*I_, MTOT, 2*I_, DIM_, 0, nullptr, nullptr, nullptr);
    conv_silu_k<<<(MTOT*I_)/256, 256>>>(conv_w, conv_b);
    tgemm<<<dim3(1,32), 256>>>(p_u, I_, W_xproj, p_params, 96, MTOT, 96, I_, 0, nullptr, nullptr, nullptr);
    tgemm<<<dim3(16,32), 256>>>(p_params, 96, W_dt, p_delta, I_, MTOT, I_, DTR_, 1, b_dt, nullptr, nullptr);
    ssm_scan_k<<<(B_*I_*N_)/256, 256>>>(A_log, Dvec);

    // join: merge GEMM needs both branches
    cudaStreamWaitEvent(0, e_join, 0);

    tgemm<<<dim3(8,32), 256>>>(p_y, I_, W_mout, p_merged, DIM_, MTOT, DIM_, I_, 2, nullptr, p_attn, m_alpha);
    tgemm<<<dim3(8,32), 256>>>(p_merged, DIM_, W_proj, out, DIM_, MTOT, DIM_, DIM_, 0, nullptr, nullptr, nullptr);
}

// round 7
// speedup vs baseline: 1.6457x; 1.0290x over previous
#include <cuda_runtime.h>
#include <math.h>
#include <stdint.h>

// ---------------- problem constants ----------------
#define B_   2
#define S_   2048
#define DIM_ 1024
#define H_   16
#define KVH_ 4
#define HD_  64
#define I_   2048
#define N_   16
#define DTR_ 64
#define K_   4
#define MTOT (B_*S_)          // 4096
#define EPSF 1.1920929e-07f

// ---------------- scratch (static device, no allocs) ----------------
__device__ float g_mp[MTOT*(size_t)(2*I_)];      // x @ W_mamba.T  (4096 x 4096)
__device__ float g_qh[MTOT*(size_t)DIM_];        // x @ W_q.T
__device__ float g_kv[MTOT*(size_t)(2*KVH_*HD_)];// x @ W_kv.T (k|v)
__device__ float g_qn[MTOT*(size_t)DIM_];        // normed+roped q
__device__ float g_kn[MTOT*(size_t)(KVH_*HD_)];  // normed+roped k
__device__ float g_attn[MTOT*(size_t)DIM_];      // attention out
__device__ float g_u[MTOT*(size_t)I_];           // conv+silu
__device__ float g_params[MTOT*(size_t)96];      // xproj out
__device__ float g_delta[MTOT*(size_t)I_];       // softplus(dt)
__device__ float g_y[MTOT*(size_t)I_];           // scan out (gated)
__device__ float g_merged[MTOT*(size_t)DIM_];    // alpha-merged
__device__ float g_rcos[S_*32];
__device__ float g_rsin[S_*32];

// ---------------- helpers ----------------
__device__ __forceinline__ float sigmoidf_(float x){ return 1.f/(1.f+expf(-x)); }
__device__ __forceinline__ float softplusf_(float x){ return fmaxf(x,0.f)+log1pf(expf(-fabsf(x))); }
__device__ __forceinline__ float tf32r_(float x){
    uint32_t u; asm("cvt.rna.tf32.f32 %0, %1;" : "=r"(u) : "f"(x));
    return __uint_as_float(u);
}
__device__ __forceinline__ uint32_t tf32u_(float x){
    uint32_t u; asm("cvt.rna.tf32.f32 %0, %1;" : "=r"(u) : "f"(x));
    return u;
}
__device__ __forceinline__ void mma_tf32_(float4& d,
    uint32_t a0, uint32_t a1, uint32_t a2, uint32_t a3,
    uint32_t b0, uint32_t b1)
{
    asm volatile("mma.sync.aligned.m16n8k8.row.col.f32.tf32.tf32.f32 "
        "{%0,%1,%2,%3}, {%4,%5,%6,%7}, {%8,%9}, {%0,%1,%2,%3};\n"
        : "+f"(d.x), "+f"(d.y), "+f"(d.z), "+f"(d.w)
        : "r"(a0), "r"(a1), "r"(a2), "r"(a3), "r"(b0), "r"(b1));
}
__device__ __forceinline__ uint32_t sptr_(const void* p){
    return (uint32_t)__cvta_generic_to_shared(p);
}
#define CP_A16(dst, src, nbytes) \
    asm volatile("cp.async.ca.shared.global [%0], [%1], 16, %2;" \
                 :: "r"(dst), "l"(src), "r"(nbytes))
#define CP_COMMIT() asm volatile("cp.async.commit_group;")
#define CP_WAIT1()  asm volatile("cp.async.wait_group 1;")

// ---------------- TF32 TC GEMM, cp.async double-buffered ----------------
// Block 128x128, K-chunk 32, 2-stage pipeline. smem tiles row-major [r][k], stride 36.
// epilogue: 0 = plain, 1 = softplus(acc + bias[c]), 2 = alpha*aux + (1-alpha)*acc
#define TG_LD 36
#define TG_STG (128*TG_LD)
#define TG_SMEM (4*TG_STG*4)   // 2 stages x (A,W) tiles, bytes (73728)

__global__ __launch_bounds__(256, 2)
void tgemm(const float* __restrict__ A, int lda,
           const float* __restrict__ W,
           float* __restrict__ C, int ldc,
           int M, int Nn, int K, int ep,
           const float* __restrict__ bias,
           const float* __restrict__ aux,
           const float* __restrict__ alpha_p)
{
    extern __shared__ float smg[];
    float* Asm[2] = { smg,            smg + TG_STG };
    float* Wsm[2] = { smg + 2*TG_STG, smg + 3*TG_STG };

    const int tid = threadIdx.x;
    const int bm = blockIdx.y * 128;
    const int bn = blockIdx.x * 128;
    const int warp = tid >> 5, lane = tid & 31;
    const int g = lane >> 2, tig = lane & 3;
    const int wm = (warp >> 2) * 64;
    const int wn = (warp & 3) * 32;

    // loader: thread covers row=tid>>1, 16 floats starting at (tid&1)*16
    const int lrow = tid >> 1;
    const int lsb  = (tid & 1) * 16;
    const float* Ag = A + (size_t)(bm + lrow) * lda + lsb;
    const int wrow_ld = ((bn + lrow) < Nn) ? (bn + lrow) : (Nn - 1);  // clamp (safe addr)
    const float* Wg = W + (size_t)wrow_ld * K + lsb;
    const int wbytes = ((bn + lrow) < Nn) ? 16 : 0;
    uint32_t dA[2], dW[2];
    #pragma unroll
    for (int st = 0; st < 2; st++) {
        dA[st] = sptr_(&Asm[st][lrow*TG_LD + lsb]);
        dW[st] = sptr_(&Wsm[st][lrow*TG_LD + lsb]);
    }

    const int NC = K >> 5;

    // prefetch chunk 0
    {
        #pragma unroll
        for (int j = 0; j < 4; j++) {
            CP_A16(dA[0] + j*16, Ag + j*4, 16);
            CP_A16(dW[0] + j*16, Wg + j*4, wbytes);
        }
        CP_COMMIT();
    }

    float4 acc[4][4];
    #pragma unroll
    for (int i = 0; i < 4; i++)
        #pragma unroll
        for (int j = 0; j < 4; j++) acc[i][j] = make_float4(0.f,0.f,0.f,0.f);

    for (int c = 0; c < NC; c++) {
        if (c + 1 < NC) {
            int st = (c+1) & 1;
            const float* Ap = Ag + (c+1)*32;
            const float* Wp = Wg + (c+1)*32;
            #pragma unroll
            for (int j = 0; j < 4; j++) {
                CP_A16(dA[st] + j*16, Ap + j*4, 16);
                CP_A16(dW[st] + j*16, Wp + j*4, wbytes);
            }
        }
        CP_COMMIT();
        CP_WAIT1();
        __syncthreads();

        const float* As = Asm[c & 1];
        const float* Ws = Wsm[c & 1];

        #pragma unroll
        for (int k0 = 0; k0 < 32; k0 += 8) {
            uint32_t af[4][4], bf[4][2];
            #pragma unroll
            for (int mt = 0; mt < 4; mt++) {
                const float* ar = &As[(wm + mt*16 + g)*TG_LD + k0 + tig];
                af[mt][0] = tf32u_(ar[0]);
                af[mt][1] = tf32u_(ar[8*TG_LD]);
                af[mt][2] = tf32u_(ar[4]);
                af[mt][3] = tf32u_(ar[8*TG_LD + 4]);
            }
            #pragma unroll
            for (int nt = 0; nt < 4; nt++) {
                const float* br = &Ws[(wn + nt*8 + g)*TG_LD + k0 + tig];
                bf[nt][0] = tf32u_(br[0]);
                bf[nt][1] = tf32u_(br[4]);
            }
            #pragma unroll
            for (int mt = 0; mt < 4; mt++)
                #pragma unroll
                for (int nt = 0; nt < 4; nt++)
                    mma_tf32_(acc[mt][nt], af[mt][0], af[mt][1], af[mt][2], af[mt][3],
                              bf[nt][0], bf[nt][1]);
        }
        __syncthreads();
    }

    float alpha = 0.f;
    if (ep == 2) alpha = sigmoidf_(alpha_p[0]);

    #pragma unroll
    for (int mt = 0; mt < 4; mt++) {
        int r0 = bm + wm + mt*16 + g;
        #pragma unroll
        for (int nt = 0; nt < 4; nt++) {
            int c0 = bn + wn + nt*8 + 2*tig;
            if (c0 < Nn) {
                float v0 = acc[mt][nt].x, v1 = acc[mt][nt].y;
                float v2 = acc[mt][nt].z, v3 = acc[mt][nt].w;
                if (ep == 1) {
                    float b0v = bias[c0], b1v = bias[c0+1];
                    v0 = softplusf_(v0 + b0v); v1 = softplusf_(v1 + b1v);
                    v2 = softplusf_(v2 + b0v); v3 = softplusf_(v3 + b1v);
                } else if (ep == 2) {
                    size_t o0 = (size_t)r0*ldc + c0, o1 = (size_t)(r0+8)*ldc + c0;
                    v0 = alpha*aux[o0]   + (1.f-alpha)*v0;
                    v1 = alpha*aux[o0+1] + (1.f-alpha)*v1;
                    v2 = alpha*aux[o1]   + (1.f-alpha)*v2;
                    v3 = alpha*aux[o1+1] + (1.f-alpha)*v3;
                }
                *(float2*)(C + (size_t)r0*ldc + c0)     = make_float2(v0, v1);
                *(float2*)(C + (size_t)(r0+8)*ldc + c0) = make_float2(v2, v3);
            }
        }
    }
}

// ---------------- RoPE tables (fp64 for accuracy) ----------------
__global__ void rope_init_k()
{
    int idx = blockIdx.x*256 + threadIdx.x;
    if (idx >= S_*32) return;
    int s = idx >> 5, d = idx & 31;
    double inv = exp(-((double)(2*d)/64.0) * log(10000.0));
    double a = (double)s * inv;
    g_rcos[idx] = (float)cos(a);
    g_rsin[idx] = (float)sin(a);
}

// ---------------- RMSNorm + RoPE (+q_gain) ----------------
__global__ __launch_bounds__(256)
void qk_norm_rope_k(const float* __restrict__ q_gain)
{
    int task = blockIdx.x*8 + (threadIdx.x >> 5);
    int lane = threadIdx.x & 31;
    int m = task / 20, hh = task % 20;
    int s = m & (S_-1);

    const float* src; float* dst;
    if (hh < 16) { src = g_qh + (size_t)m*DIM_ + hh*64; dst = g_qn + (size_t)m*DIM_ + hh*64; }
    else         { src = g_kv + (size_t)m*512 + (hh-16)*64; dst = g_kn + (size_t)m*256 + (hh-16)*64; }

    float v0 = src[lane], v1 = src[lane+32];
    float ss = v0*v0 + v1*v1;
    #pragma unroll
    for (int off = 16; off >= 1; off >>= 1) ss += __shfl_xor_sync(0xffffffffu, ss, off);
    float r = rsqrtf(ss/64.f + EPSF);
    v0 *= r; v1 *= r;
    float c  = g_rcos[s*32 + lane];
    float sn = g_rsin[s*32 + lane];
    float o0 =  v0*c + v1*sn;
    float o1 = -v0*sn + v1*c;
    if (hh < 16) { float g = q_gain[hh]; o0 *= g; o1 *= g; }
    dst[lane] = o0; dst[lane+32] = o1;
}

// ---------------- TF32 TC causal flash attention, cp.async double-buffered ----------------
// Q tile 128 (8 warps x 16 rows), K tile 64, 2-stage K/V prefetch.
// smem floats: K[2][64*68], V[2][64*68], P[128*68]  -> 26112 floats = 104448 bytes
#define FA_KS0 0
#define FA_KS1 (64*68)
#define FA_VS0 (2*64*68)
#define FA_VS1 (3*64*68)
#define FA_PS  (4*64*68)
#define FA_SMEM ((4*64*68 + 128*68)*4)

__global__ __launch_bounds__(256)
void flash_attn_tc()
{
    extern __shared__ float sm[];
    float* Kbuf[2] = { sm + FA_KS0, sm + FA_KS1 };
    float* Vbuf[2] = { sm + FA_VS0, sm + FA_VS1 };
    float* Ps = sm + FA_PS;

    const int tid = threadIdx.x;
    const int warp = tid >> 5, lane = tid & 31;
    const int g = lane >> 2, tig = lane & 3;
    const int qx = (gridDim.x - 1) - blockIdx.x;   // heavy tiles first
    const int h = blockIdx.y, b = blockIdx.z;
    const int kh = h >> 2;
    const int q0 = qx * 128;
    const int wrow = warp * 16;
    const int r0g = q0 + wrow + g, r1g = r0g + 8;

    // persistent Q fragments (tf32), pre-scaled by 1/sqrt(d)=0.125
    uint32_t qf[8][4];
    {
        const float* Qb = g_qn + ((size_t)(b*S_ + q0 + wrow))*DIM_ + h*64;
        #pragma unroll
        for (int ch = 0; ch < 8; ch++) {
            qf[ch][0] = tf32u_(0.125f * Qb[(size_t)(g  )*DIM_ + ch*8 + tig    ]);
            qf[ch][1] = tf32u_(0.125f * Qb[(size_t)(g+8)*DIM_ + ch*8 + tig    ]);
            qf[ch][2] = tf32u_(0.125f * Qb[(size_t)(g  )*DIM_ + ch*8 + tig + 4]);
            qf[ch][3] = tf32u_(0.125f * Qb[(size_t)(g+8)*DIM_ + ch*8 + tig + 4]);
        }
    }

    float4 of[8];
    #pragma unroll
    for (int nb = 0; nb < 8; nb++) of[nb] = make_float4(0.f,0.f,0.f,0.f);
    float m0 = -1e30f, m1 = -1e30f, l0 = 0.f, l1 = 0.f;

    const int KT = 2*qx + 2;

    // K/V loader: thread covers row=tid>>2, 16 floats at (tid&3)*16
    const int lrow = tid >> 2;
    const int lsb  = (tid & 3) * 16;
    uint32_t dK[2], dV[2];
    #pragma unroll
    for (int st = 0; st < 2; st++) {
        dK[st] = sptr_(&Kbuf[st][lrow*68 + lsb]);
        dV[st] = sptr_(&Vbuf[st][lrow*68 + lsb]);
    }

    // prefetch tile 0
    {
        size_t krow = (size_t)(b*S_ + lrow);
        const float* kp = g_kn + krow*256 + kh*64 + lsb;
        const float* vp = g_kv + krow*512 + 256 + kh*64 + lsb;
        #pragma unroll
        for (int j = 0; j < 4; j++) {
            CP_A16(dK[0] + j*16, kp + j*4, 16);
            CP_A16(dV[0] + j*16, vp + j*4, 16);
        }
        CP_COMMIT();
    }

    for (int kt = 0; kt < KT; kt++) {
        if (kt + 1 < KT) {
            int st = (kt+1) & 1;
            size_t krow = (size_t)(b*S_ + (kt+1)*64 + lrow);
            const float* kp = g_kn + krow*256 + kh*64 + lsb;
            const float* vp = g_kv + krow*512 + 256 + kh*64 + lsb;
            #pragma unroll
            for (int j = 0; j < 4; j++) {
                CP_A16(dK[st] + j*16, kp + j*4, 16);
                CP_A16(dV[st] + j*16, vp + j*4, 16);
            }
        }
        CP_COMMIT();
        CP_WAIT1();
        __syncthreads();

        const float* Ks = Kbuf[kt & 1];
        const float* Vs = Vbuf[kt & 1];
        const int ktb = kt*64;

        if (ktb <= q0 + wrow + 15) {      // warp has at least one unmasked row
            // ---- S = (Q/8) K^T ----
            float4 sc[8];
            #pragma unroll
            for (int nb = 0; nb < 8; nb++) sc[nb] = make_float4(0.f,0.f,0.f,0.f);
            #pragma unroll
            for (int ch = 0; ch < 8; ch++) {
                const int k0 = ch*8;
                #pragma unroll
                for (int nb = 0; nb < 8; nb++) {
                    uint32_t b0 = tf32u_(Ks[(nb*8+g)*68 + k0 + tig    ]);
                    uint32_t b1 = tf32u_(Ks[(nb*8+g)*68 + k0 + tig + 4]);
                    mma_tf32_(sc[nb], qf[ch][0], qf[ch][1], qf[ch][2], qf[ch][3], b0, b1);
                }
            }
            // mask
            if ((ktb + 63) > r0g) {
                #pragma unroll
                for (int nb = 0; nb < 8; nb++) {
                    int c0 = ktb + nb*8 + 2*tig, c1 = c0 + 1;
                    if (c0 > r0g) sc[nb].x = -1e30f;
                    if (c1 > r0g) sc[nb].y = -1e30f;
                    if (c0 > r1g) sc[nb].z = -1e30f;
                    if (c1 > r1g) sc[nb].w = -1e30f;
                }
            }
            // ---- online softmax ----
            float rm0 = -1e30f, rm1 = -1e30f;
            #pragma unroll
            for (int nb = 0; nb < 8; nb++) {
                rm0 = fmaxf(rm0, fmaxf(sc[nb].x, sc[nb].y));
                rm1 = fmaxf(rm1, fmaxf(sc[nb].z, sc[nb].w));
            }
            rm0 = fmaxf(rm0, __shfl_xor_sync(0xffffffffu, rm0, 1));
            rm0 = fmaxf(rm0, __shfl_xor_sync(0xffffffffu, rm0, 2));
            rm1 = fmaxf(rm1, __shfl_xor_sync(0xffffffffu, rm1, 1));
            rm1 = fmaxf(rm1, __shfl_xor_sync(0xffffffffu, rm1, 2));
            float nm0 = fmaxf(m0, rm0), nm1 = fmaxf(m1, rm1);
            float corr0 = __expf(m0 - nm0), corr1 = __expf(m1 - nm1);
            float rs0 = 0.f, rs1 = 0.f;
            #pragma unroll
            for (int nb = 0; nb < 8; nb++) {
                sc[nb].x = __expf(sc[nb].x - nm0);
                sc[nb].y = __expf(sc[nb].y - nm0);
                sc[nb].z = __expf(sc[nb].z - nm1);
                sc[nb].w = __expf(sc[nb].w - nm1);
                rs0 += sc[nb].x + sc[nb].y;
                rs1 += sc[nb].z + sc[nb].w;
            }
            rs0 += __shfl_xor_sync(0xffffffffu, rs0, 1);
            rs0 += __shfl_xor_sync(0xffffffffu, rs0, 2);
            rs1 += __shfl_xor_sync(0xffffffffu, rs1, 1);
            rs1 += __shfl_xor_sync(0xffffffffu, rs1, 2);
            l0 = l0*corr0 + rs0; l1 = l1*corr1 + rs1;
            m0 = nm0; m1 = nm1;
            #pragma unroll
            for (int nb = 0; nb < 8; nb++) {
                of[nb].x *= corr0; of[nb].y *= corr0;
                of[nb].z *= corr1; of[nb].w *= corr1;
            }
            // ---- P -> smem (warp-private rows), tf32 rounded ----
            #pragma unroll
            for (int nb = 0; nb < 8; nb++) {
                *(float2*)&Ps[(wrow+g  )*68 + nb*8 + 2*tig] =
                    make_float2(tf32r_(sc[nb].x), tf32r_(sc[nb].y));
                *(float2*)&Ps[(wrow+g+8)*68 + nb*8 + 2*tig] =
                    make_float2(tf32r_(sc[nb].z), tf32r_(sc[nb].w));
            }
            __syncwarp();
            // ---- O += P V ----
            #pragma unroll
            for (int ch = 0; ch < 8; ch++) {
                const int kc = ch*8;
                uint32_t a0 = __float_as_uint(Ps[(wrow+g  )*68 + kc + tig    ]);
                uint32_t a1 = __float_as_uint(Ps[(wrow+g+8)*68 + kc + tig    ]);
                uint32_t a2 = __float_as_uint(Ps[(wrow+g  )*68 + kc + tig + 4]);
                uint32_t a3 = __float_as_uint(Ps[(wrow+g+8)*68 + kc + tig + 4]);
                #pragma unroll
                for (int nb = 0; nb < 8; nb++) {
                    uint32_t b0 = tf32u_(Vs[(kc+tig  )*68 + nb*8 + g]);
                    uint32_t b1 = tf32u_(Vs[(kc+tig+4)*68 + nb*8 + g]);
                    mma_tf32_(of[nb], a0, a1, a2, a3, b0, b1);
                }
            }
        }
        __syncthreads();
    }

    // ---- normalize + store ----
    float inv0 = 1.f / l0, inv1 = 1.f / l1;
    float* O0 = g_attn + (size_t)(b*S_ + r0g)*DIM_ + h*64;
    float* O1 = g_attn + (size_t)(b*S_ + r1g)*DIM_ + h*64;
    #pragma unroll
    for (int nb = 0; nb < 8; nb++) {
        *(float2*)(O0 + nb*8 + 2*tig) = make_float2(of[nb].x*inv0, of[nb].y*inv0);
        *(float2*)(O1 + nb*8 + 2*tig) = make_float2(of[nb].z*inv1, of[nb].w*inv1);
    }
}

// ---------------- depthwise causal conv (K=4) + SiLU ----------------
__global__ __launch_bounds__(256)
void conv_silu_k(const float* __restrict__ conv_w, const float* __restrict__ conv_b)
{
    int idx = blockIdx.x*256 + threadIdx.x;
    int m = idx >> 11, i = idx & (I_-1);
    int b = m >> 11, s = m & (S_-1);
    float acc = conv_b[i];
    #pragma unroll
    for (int k = 0; k < K_; k++) {
        int sp = s - 3 + k;
        if (sp >= 0) acc += g_mp[((size_t)(b*S_ + sp))*(2*I_) + i] * conv_w[i*K_ + k];
    }
    g_u[idx] = acc * sigmoidf_(acc);
}

// ---------------- SSM sequential scan, fused D/gate epilogue ----------------
__global__ __launch_bounds__(256)
void ssm_scan_k(const float* __restrict__ A_log, const float* __restrict__ Dvec)
{
    int gtid = blockIdx.x*256 + threadIdx.x;
    int grp = gtid >> 4, n = gtid & 15;
    int b = grp >> 11, i = grp & (I_-1);

    float A  = -expf(A_log[i*N_ + n]);
    float Dv = Dvec[i];
    float state = 0.f;
    size_t base = (size_t)b * S_;

    for (int t = 0; t < S_; t++) {
        size_t m = base + t;
        float d  = g_delta[m*I_ + i];
        float uu = g_u[m*I_ + i];
        float Bv = g_params[m*96 + 64 + n];
        float Cv = g_params[m*96 + 80 + n];
        state = state*expf(d*A) + d*Bv*uu;
        float yv = state*Cv;
        #pragma unroll
        for (int off = 8; off >= 1; off >>= 1) yv += __shfl_xor_sync(0xffffffffu, yv, off);
        if (n == 0) {
            float g = g_mp[m*(2*I_) + I_ + i];
            g_y[m*I_ + i] = (yv + uu*Dv) * g * sigmoidf_(g);
        }
    }
}

// ---------------- launcher (stream fork/join for branch concurrency) ----------------
extern "C" void kernel_launch(void* const* d_in, const int* in_sizes, int n_in,
                              void* d_out, int out_size)
{
    const float* x        = (const float*)d_in[0];
    const float* W_mamba  = (const float*)d_in[1];
    const float* W_q      = (const float*)d_in[2];
    const float* W_kv     = (const float*)d_in[3];
    const float* q_gain   = (const float*)d_in[4];
    const float* conv_w   = (const float*)d_in[5];
    const float* conv_b   = (const float*)d_in[6];
    const float* W_xproj  = (const float*)d_in[7];
    const float* W_dt     = (const float*)d_in[8];
    const float* b_dt     = (const float*)d_in[9];
    const float* A_log    = (const float*)d_in[10];
    const float* Dvec     = (const float*)d_in[11];
    const float* W_mout   = (const float*)d_in[12];
    const float* W_proj   = (const float*)d_in[13];
    const float* m_alpha  = (const float*)d_in[14];
    float* out = (float*)d_out;

    float *p_mp, *p_qh, *p_kv, *p_attn, *p_u, *p_params, *p_delta, *p_y, *p_merged;
    cudaGetSymbolAddress((void**)&p_mp, g_mp);
    cudaGetSymbolAddress((void**)&p_qh, g_qh);
    cudaGetSymbolAddress((void**)&p_kv, g_kv);
    cudaGetSymbolAddress((void**)&p_attn, g_attn);
    cudaGetSymbolAddress((void**)&p_u, g_u);
    cudaGetSymbolAddress((void**)&p_params, g_params);
    cudaGetSymbolAddress((void**)&p_delta, g_delta);
    cudaGetSymbolAddress((void**)&p_y, g_y);
    cudaGetSymbolAddress((void**)&p_merged, g_merged);

    cudaFuncSetAttribute(flash_attn_tc, cudaFuncAttributeMaxDynamicSharedMemorySize, FA_SMEM);
    cudaFuncSetAttribute(tgemm, cudaFuncAttributeMaxDynamicSharedMemorySize, TG_SMEM);

    cudaStream_t s1;
    cudaStreamCreate(&s1);
    cudaEvent_t e_fork, e_join;
    cudaEventCreateWithFlags(&e_fork, cudaEventDisableTiming);
    cudaEventCreateWithFlags(&e_join, cudaEventDisableTiming);

    cudaEventRecord(e_fork, 0);
    cudaStreamWaitEvent(s1, e_fork, 0);

    // ---- side branch (attention path) on s1 ----
    rope_init_k<<<(S_*32 + 255)/256, 256, 0, s1>>>();
    tgemm<<<dim3(8,32), 256, TG_SMEM, s1>>>(x, DIM_, W_q, p_qh, DIM_, MTOT, DIM_, DIM_, 0, nullptr, nullptr, nullptr);
    tgemm<<<dim3(4,32), 256, TG_SMEM, s1>>>(x, DIM_, W_kv, p_kv, 512, MTOT, 512, DIM_, 0, nullptr, nullptr, nullptr);
    qk_norm_rope_k<<<(MTOT*20)/8, 256, 0, s1>>>(q_gain);
    flash_attn_tc<<<dim3(S_/128, H_, B_), 256, FA_SMEM, s1>>>();
    cudaEventRecord(e_join, s1);

    // ---- main branch (mamba path) on default stream ----
    tgemm<<<dim3(32,32), 256, TG_SMEM>>>(x, DIM_, W_mamba, p_mp, 2*I_, MTOT, 2*I_, DIM_, 0, nullptr, nullptr, nullptr);
    conv_silu_k<<<(MTOT*I_)/256, 256>>>(conv_w, conv_b);
    tgemm<<<dim3(1,32), 256, TG_SMEM>>>(p_u, I_, W_xproj, p_params, 96, MTOT, 96, I_, 0, nullptr, nullptr, nullptr);
    tgemm<<<dim3(16,32), 256, TG_SMEM>>>(p_params, 96, W_dt, p_delta, I_, MTOT, I_, DTR_, 1, b_dt, nullptr, nullptr);
    ssm_scan_k<<<(B_*I_*N_)/256, 256>>>(A_log, Dvec);

    cudaStreamWaitEvent(0, e_join, 0);

    tgemm<<<dim3(8,32), 256, TG_SMEM>>>(p_y, I_, W_mout, p_merged, DIM_, MTOT, DIM_, I_, 2, nullptr, p_attn, m_alpha);
    tgemm<<<dim3(8,32), 256, TG_SMEM>>>(p_merged, DIM_, W_proj, out, DIM_, MTOT, DIM_, DIM_, 0, nullptr, nullptr, nullptr);
}